// round 4
// baseline (speedup 1.0000x reference)
#include <cuda_runtime.h>
#include <math.h>

#define NDIM    64
#define LD      65            // padded row stride (floats) for A/V in smem
#define NMAT    4096
#define NDOMS   8
#define MATSZ   (NDIM*NDIM)   // 4096
#define BUF     (NDIM*LD)     // 4160 floats per smem matrix buffer
#define NSWEEPS 8
#define EIG_EPS 1e-4f
#define EPS_C   1e-5f
#define ETA_C   1.0f

// ---------------- device scratch (no allocations allowed) ----------------
__device__ float g_bmsum [NDOMS*MATSZ];
__device__ float g_bm_sq [NDOMS*MATSZ];
__device__ float g_bm_isq[NDOMS*MATSZ];
__device__ float g_GT    [NDOMS*MATSZ];
__device__ float g_rm_isq[NDOMS*MATSZ];
__device__ float g_Bsq   [MATSZ];
__device__ float g_sumsq [NDOMS];
__device__ float g_cnt   [NDOMS];
__device__ float g_s     [NDOMS];

// ---------------- helpers ----------------
__device__ __forceinline__ float blockReduceSum(float v) {
    __shared__ float red[8];
    const unsigned m = 0xffffffffu;
    #pragma unroll
    for (int o = 16; o; o >>= 1) v += __shfl_down_sync(m, v, o);
    if ((threadIdx.x & 31) == 0) red[threadIdx.x >> 5] = v;
    __syncthreads();
    if (threadIdx.x < 32) {
        float x = (threadIdx.x < 8) ? red[threadIdx.x] : 0.0f;
        #pragma unroll
        for (int o = 4; o; o >>= 1) x += __shfl_down_sync(m, x, o);
        if (threadIdx.x == 0) red[0] = x;
    }
    __syncthreads();
    float r = red[0];
    __syncthreads();
    return r;
}

// C(64x64) = A * B   (or A * B^T).  A,B in smem with stride LD.
// C may be smem (ldc=LD) or global row-major (ldc=64).
template<bool TRANSB>
__device__ __forceinline__ void mm64(const float* __restrict__ A,
                                     const float* __restrict__ B,
                                     float* __restrict__ C, int ldc) {
    const int tid = threadIdx.x;
    const int r0 = (tid >> 4) << 2;   // 16 row groups of 4
    const int c0 = (tid & 15) << 2;   // 16 col groups of 4
    float acc[4][4];
    #pragma unroll
    for (int i = 0; i < 4; i++)
        #pragma unroll
        for (int j = 0; j < 4; j++) acc[i][j] = 0.0f;
    #pragma unroll 4
    for (int k = 0; k < 64; k++) {
        float a0 = A[(r0+0)*LD + k];
        float a1 = A[(r0+1)*LD + k];
        float a2 = A[(r0+2)*LD + k];
        float a3 = A[(r0+3)*LD + k];
        float b0, b1, b2, b3;
        if (TRANSB) {
            b0 = B[(c0+0)*LD + k]; b1 = B[(c0+1)*LD + k];
            b2 = B[(c0+2)*LD + k]; b3 = B[(c0+3)*LD + k];
        } else {
            b0 = B[k*LD + c0+0]; b1 = B[k*LD + c0+1];
            b2 = B[k*LD + c0+2]; b3 = B[k*LD + c0+3];
        }
        acc[0][0] += a0*b0; acc[0][1] += a0*b1; acc[0][2] += a0*b2; acc[0][3] += a0*b3;
        acc[1][0] += a1*b0; acc[1][1] += a1*b1; acc[1][2] += a1*b2; acc[1][3] += a1*b3;
        acc[2][0] += a2*b0; acc[2][1] += a2*b1; acc[2][2] += a2*b2; acc[2][3] += a2*b3;
        acc[3][0] += a3*b0; acc[3][1] += a3*b1; acc[3][2] += a3*b2; acc[3][3] += a3*b3;
    }
    #pragma unroll
    for (int i = 0; i < 4; i++)
        #pragma unroll
        for (int j = 0; j < 4; j++)
            C[(size_t)(r0+i)*ldc + c0 + j] = acc[i][j];
}

__device__ __forceinline__ void symmetrize(const float* __restrict__ S, float* __restrict__ D) {
    for (int i = threadIdx.x; i < MATSZ; i += 256) {
        int r = i >> 6, c = i & 63;
        D[r*LD+c] = 0.5f*(S[r*LD+c] + S[c*LD+r]);
    }
}

// Block-parallel cyclic Jacobi eigensolver. A (symmetric, smem, stride LD) is
// diagonalized in place; V accumulates eigenvectors (A_in = V diag(A_out) V^T).
// 256 threads. Round-robin tournament ordering, 63 rounds/sweep, fixed sweeps.
__device__ void jacobi_eig(float* A, float* V) {
    __shared__ float sc[32], ss[32];
    __shared__ int   spv[32], sqv[32];
    const int tid = threadIdx.x;
    for (int i = tid; i < MATSZ; i += 256) {
        int r = i >> 6, c = i & 63;
        V[r*LD+c] = (r == c) ? 1.0f : 0.0f;
    }
    __syncthreads();
    for (int sw = 0; sw < NSWEEPS; sw++) {
        for (int rd = 0; rd < 63; rd++) {
            if (tid < 32) {
                // closed-form round-robin pairing: x solves 2x == rd (mod 63)
                int x = (rd * 32) % 63;
                int p, q;
                if (tid == 0) { p = x; q = 63; }
                else {
                    int a = x + tid;      if (a >= 63) a -= 63;
                    int b = x - tid;      if (b < 0)   b += 63;
                    p = min(a, b); q = max(a, b);
                }
                spv[tid] = p; sqv[tid] = q;
                float apq = A[p*LD+q];
                float c, s;
                if (fabsf(apq) > 1e-30f) {
                    float app = A[p*LD+p], aqq = A[q*LD+q];
                    float tau = (aqq - app) / (2.0f * apq);
                    float t   = 1.0f / (fabsf(tau) + sqrtf(1.0f + tau*tau));
                    if (tau < 0.0f) t = -t;
                    c = 1.0f / sqrtf(1.0f + t*t);
                    s = t * c;
                } else { c = 1.0f; s = 0.0f; }
                sc[tid] = c; ss[tid] = s;
            }
            __syncthreads();
            const int slot = tid >> 3;
            const int p = spv[slot], q = sqv[slot];
            const float c = sc[slot], s = ss[slot];
            const int k0 = tid & 7;
            // row phase: A <- J^T A
            #pragma unroll
            for (int j = 0; j < 8; j++) {
                int k = k0 + 8*j;
                float ap = A[p*LD+k], aq = A[q*LD+k];
                A[p*LD+k] = c*ap - s*aq;
                A[q*LD+k] = s*ap + c*aq;
            }
            __syncthreads();
            // col phase: A <- A J ;  V <- V J
            #pragma unroll
            for (int j = 0; j < 8; j++) {
                int k = k0 + 8*j;
                float ap = A[k*LD+p], aq = A[k*LD+q];
                A[k*LD+p] = c*ap - s*aq;
                A[k*LD+q] = s*ap + c*aq;
                float vp = V[k*LD+p], vq = V[k*LD+q];
                V[k*LD+p] = c*vp - s*vq;
                V[k*LD+q] = s*vp + c*vq;
            }
            __syncthreads();
        }
    }
}

// ---------------- kernels ----------------
__global__ void kzero_kernel() {
    int i = blockIdx.x * blockDim.x + threadIdx.x;
    int stride = gridDim.x * blockDim.x;
    for (int j = i; j < NDOMS*MATSZ; j += stride) { g_bmsum[j] = 0.0f; g_GT[j] = 0.0f; }
    if (i < NDOMS) g_sumsq[i] = 0.0f;
}

// per-domain sums of X  (bm numerator)
__global__ void __launch_bounds__(256) k1_kernel(const float* __restrict__ X,
                                                 const int* __restrict__ dd) {
    __shared__ int sdom[128];
    const int e  = blockIdx.x * 256 + threadIdx.x;   // element position 0..4095
    const int n0 = blockIdx.y * 128;                 // matrix chunk
    if (threadIdx.x < 128) sdom[threadIdx.x] = dd[n0 + threadIdx.x];
    __syncthreads();
    float acc[NDOMS];
    #pragma unroll
    for (int k = 0; k < NDOMS; k++) acc[k] = 0.0f;
    for (int m = 0; m < 128; m++) {
        float x = X[(size_t)(n0 + m) * MATSZ + e];
        int dom = sdom[m];
        #pragma unroll
        for (int k = 0; k < NDOMS; k++) acc[k] += (dom == k) ? x : 0.0f;
    }
    #pragma unroll
    for (int k = 0; k < NDOMS; k++) atomicAdd(&g_bmsum[k*MATSZ + e], acc[k]);
}

// per-domain: cnt, bm = sum/cnt, eig(bm) -> bm_sq, bm_isq
__global__ void __launch_bounds__(256) k2_kernel(const int* __restrict__ dd) {
    extern __shared__ float sm[];
    float* SX = sm;               // raw / W
    float* SA = sm + BUF;         // eig workspace
    float* SV = sm + 2*BUF;       // eigenvectors
    __shared__ float sl[64];
    const int dom = blockIdx.x, tid = threadIdx.x;

    float loc = 0.0f;
    for (int i = tid; i < NMAT; i += 256) loc += (dd[i] == dom) ? 1.0f : 0.0f;
    float cnt  = blockReduceSum(loc);
    float cntf = fmaxf(cnt, 1.0f);
    if (tid == 0) g_cnt[dom] = cntf;

    for (int i = tid; i < MATSZ; i += 256) {
        int r = i >> 6, c = i & 63;
        SX[r*LD+c] = g_bmsum[dom*MATSZ + i] / cntf;
    }
    __syncthreads();
    symmetrize(SX, SA);
    __syncthreads();
    jacobi_eig(SA, SV);
    if (tid < 64) sl[tid] = fmaxf(SA[tid*LD+tid], EIG_EPS);
    __syncthreads();
    for (int i = tid; i < MATSZ; i += 256) {
        int r = i >> 6, c = i & 63;
        SX[r*LD+c] = SV[r*LD+c] * sqrtf(sl[c]);
    }
    __syncthreads();
    mm64<true>(SX, SV, g_bm_sq + dom*MATSZ, 64);
    __syncthreads();
    for (int i = tid; i < MATSZ; i += 256) {
        int r = i >> 6, c = i & 63;
        SX[r*LD+c] = SV[r*LD+c] / sqrtf(sl[c]);
    }
    __syncthreads();
    mm64<true>(SX, SV, g_bm_isq + dom*MATSZ, 64);
}

// per-element: XT = logm(bm_isq X bm_isq); accumulate GT sums + sum||XT||^2
__global__ void __launch_bounds__(256) k3_kernel(const float* __restrict__ X,
                                                 const int* __restrict__ dd) {
    extern __shared__ float sm[];
    float* SX = sm;           float* SQ = sm + BUF;
    float* SA = sm + 2*BUF;   float* SV = sm + 3*BUF;
    __shared__ float sl[64];
    const int n = blockIdx.x, tid = threadIdx.x;
    const int dom = dd[n];
    const float* xg = X + (size_t)n * MATSZ;
    const float* qg = g_bm_isq + dom * MATSZ;
    for (int i = tid; i < MATSZ; i += 256) {
        int r = i >> 6, c = i & 63;
        SX[r*LD+c] = xg[i];
        SQ[r*LD+c] = qg[i];
    }
    __syncthreads();
    mm64<false>(SQ, SX, SA, LD);   __syncthreads();   // T = Q X
    mm64<false>(SA, SQ, SV, LD);   __syncthreads();   // M = T Q
    symmetrize(SV, SA);            __syncthreads();
    jacobi_eig(SA, SV);
    if (tid < 64) sl[tid] = logf(fmaxf(SA[tid*LD+tid], EIG_EPS));
    __syncthreads();
    for (int i = tid; i < MATSZ; i += 256) {
        int r = i >> 6, c = i & 63;
        SX[r*LD+c] = SV[r*LD+c] * sl[c];
    }
    __syncthreads();
    mm64<true>(SX, SV, SQ, LD);    __syncthreads();   // XT = W V^T
    float* gt = g_GT + dom * MATSZ;
    float loc = 0.0f;
    for (int i = tid; i < MATSZ; i += 256) {
        int r = i >> 6, c = i & 63;
        float v = SQ[r*LD+c];
        atomicAdd(&gt[i], v);
        loc += v * v;
    }
    float tot = blockReduceSum(loc);
    if (tid == 0) atomicAdd(&g_sumsq[dom], tot);
}

// per-domain update: bm_new, rm, rm_isq, GT2, batch_var, s.  Block 8: B_sq = sqrtm(mean).
__global__ void __launch_bounds__(256) k4_kernel(const float* __restrict__ mean,
                                                 const float* __restrict__ stdv) {
    extern __shared__ float sm[];
    float* SA = sm;           float* SV = sm + BUF;
    float* SQ = sm + 2*BUF;   float* SX = sm + 3*BUF;
    float* SG = sm + 4*BUF;
    __shared__ float sl[64];
    const int tid = threadIdx.x, b = blockIdx.x;

    if (b == NDOMS) {  // B_sq = sqrtm(mean)
        for (int i = tid; i < MATSZ; i += 256) { int r=i>>6,c=i&63; SX[r*LD+c] = mean[i]; }
        __syncthreads();
        symmetrize(SX, SA); __syncthreads();
        jacobi_eig(SA, SV);
        if (tid < 64) sl[tid] = sqrtf(fmaxf(SA[tid*LD+tid], EIG_EPS));
        __syncthreads();
        for (int i = tid; i < MATSZ; i += 256) { int r=i>>6,c=i&63; SX[r*LD+c] = SV[r*LD+c]*sl[c]; }
        __syncthreads();
        mm64<true>(SX, SV, g_Bsq, 64);
        return;
    }
    const int dom = b;
    const float cntf = g_cnt[dom];
    // GT
    for (int i = tid; i < MATSZ; i += 256) { int r=i>>6,c=i&63; SG[r*LD+c] = g_GT[dom*MATSZ+i] / cntf; }
    __syncthreads();
    symmetrize(SG, SA); __syncthreads();
    jacobi_eig(SA, SV);                               // eig(GT)
    if (tid < 64) sl[tid] = expf(SA[tid*LD+tid]);
    __syncthreads();
    for (int i = tid; i < MATSZ; i += 256) { int r=i>>6,c=i&63; SX[r*LD+c] = SV[r*LD+c]*sl[c]; }
    __syncthreads();
    mm64<true>(SX, SV, SQ, LD); __syncthreads();      // E = expm(GT)
    for (int i = tid; i < MATSZ; i += 256) { int r=i>>6,c=i&63; SA[r*LD+c] = g_bm_sq[dom*MATSZ+i]; }
    __syncthreads();
    mm64<false>(SA, SQ, SX, LD); __syncthreads();     // bm_sq E
    mm64<false>(SX, SA, SV, LD); __syncthreads();     // bm_new -> SV
    symmetrize(SV, SA); __syncthreads();
    jacobi_eig(SA, SQ);                               // eig(bm_new), U in SQ
    if (tid < 64) sl[tid] = fmaxf(SA[tid*LD+tid], EIG_EPS);   // lam_rm = exp(log(clip)) = clip
    __syncthreads();
    for (int i = tid; i < MATSZ; i += 256) { int r=i>>6,c=i&63; SX[r*LD+c] = SQ[r*LD+c]*sl[c]; }
    __syncthreads();
    mm64<true>(SX, SQ, SV, LD); __syncthreads();      // rm -> SV
    for (int i = tid; i < MATSZ; i += 256) { int r=i>>6,c=i&63; SX[r*LD+c] = SQ[r*LD+c]/sqrtf(sl[c]); }
    __syncthreads();
    mm64<true>(SX, SQ, g_rm_isq + dom*MATSZ, 64); __syncthreads();   // rm_isq -> global
    for (int i = tid; i < MATSZ; i += 256) { int r=i>>6,c=i&63; SA[r*LD+c] = g_bm_isq[dom*MATSZ+i]; }
    __syncthreads();
    mm64<false>(SA, SV, SX, LD); __syncthreads();     // bm_isq rm
    mm64<false>(SX, SA, SV, LD); __syncthreads();     // T1 -> SV
    symmetrize(SV, SA); __syncthreads();
    jacobi_eig(SA, SQ);                               // eig(T1)
    if (tid < 64) sl[tid] = logf(fmaxf(SA[tid*LD+tid], EIG_EPS));
    __syncthreads();
    for (int i = tid; i < MATSZ; i += 256) { int r=i>>6,c=i&63; SX[r*LD+c] = SQ[r*LD+c]*sl[c]; }
    __syncthreads();
    mm64<true>(SX, SQ, SV, LD); __syncthreads();      // GT2 -> SV
    float l1 = 0.0f, l2 = 0.0f;
    for (int i = tid; i < MATSZ; i += 256) {
        int r = i >> 6, c = i & 63;
        float g2 = SV[r*LD+c], g = SG[r*LD+c];
        l1 += g * g2; l2 += g2 * g2;
    }
    float dt = blockReduceSum(l1);
    float n2 = blockReduceSum(l2);
    if (tid == 0) {
        // sum ||XT - GT2||^2 / cnt = sumsq/cnt - 2<GT,GT2> + ||GT2||^2  (exact algebra)
        float var = g_sumsq[dom] / cntf - 2.0f * dt + n2;
        float rv  = (1.0f - ETA_C) * 1.0f + ETA_C * var;
        g_s[dom]  = stdv[0] / sqrtf(rv + EPS_C);
    }
}

// per-element: Xn = B_sq * (rm_isq X rm_isq)^s * B_sq
__global__ void __launch_bounds__(256) k5_kernel(const float* __restrict__ X,
                                                 const int* __restrict__ dd,
                                                 float* __restrict__ out) {
    extern __shared__ float sm[];
    float* SX = sm;           float* SQ = sm + BUF;
    float* SA = sm + 2*BUF;   float* SV = sm + 3*BUF;
    __shared__ float sl[64];
    const int n = blockIdx.x, tid = threadIdx.x;
    const int dom = dd[n];
    const float* xg = X + (size_t)n * MATSZ;
    const float* qg = g_rm_isq + dom * MATSZ;
    for (int i = tid; i < MATSZ; i += 256) {
        int r = i >> 6, c = i & 63;
        SX[r*LD+c] = xg[i];
        SQ[r*LD+c] = qg[i];
    }
    __syncthreads();
    mm64<false>(SQ, SX, SA, LD);   __syncthreads();
    mm64<false>(SA, SQ, SV, LD);   __syncthreads();
    symmetrize(SV, SA);            __syncthreads();
    jacobi_eig(SA, SV);
    const float sgl = g_s[dom];
    if (tid < 64) sl[tid] = expf(sgl * logf(fmaxf(SA[tid*LD+tid], EIG_EPS)));
    __syncthreads();
    for (int i = tid; i < MATSZ; i += 256) {
        int r = i >> 6, c = i & 63;
        SX[r*LD+c] = SV[r*LD+c] * sl[c];
    }
    __syncthreads();
    mm64<true>(SX, SV, SQ, LD);    __syncthreads();   // P = expm(s * inner)
    for (int i = tid; i < MATSZ; i += 256) { int r=i>>6,c=i&63; SA[r*LD+c] = g_Bsq[i]; }
    __syncthreads();
    mm64<false>(SA, SQ, SV, LD);   __syncthreads();   // B_sq P
    mm64<false>(SV, SA, out + (size_t)n * MATSZ, 64); // Xn -> global
}

// ---------------- launch ----------------
extern "C" void kernel_launch(void* const* d_in, const int* in_sizes, int n_in,
                              void* d_out, int out_size) {
    const float* X    = (const float*)d_in[0];
    const int*   dd   = (const int*)  d_in[1];
    const float* mean = (const float*)d_in[2];
    const float* stdv = (const float*)d_in[3];
    float* out = (float*)d_out;

    const int SM4 = 4 * BUF * (int)sizeof(float);   // 66560 B
    const int SM5 = 5 * BUF * (int)sizeof(float);   // 83200 B
    cudaFuncSetAttribute(k2_kernel, cudaFuncAttributeMaxDynamicSharedMemorySize, SM4);
    cudaFuncSetAttribute(k3_kernel, cudaFuncAttributeMaxDynamicSharedMemorySize, SM4);
    cudaFuncSetAttribute(k4_kernel, cudaFuncAttributeMaxDynamicSharedMemorySize, SM5);
    cudaFuncSetAttribute(k5_kernel, cudaFuncAttributeMaxDynamicSharedMemorySize, SM4);

    kzero_kernel<<<128, 256>>>();
    k1_kernel<<<dim3(16, 32), 256>>>(X, dd);
    k2_kernel<<<NDOMS, 256, SM4>>>(dd);
    k3_kernel<<<NMAT, 256, SM4>>>(X, dd);
    k4_kernel<<<NDOMS + 1, 256, SM5>>>(mean, stdv);
    k5_kernel<<<NMAT, 256, SM4>>>(X, dd, out);
}

// round 5
// speedup vs baseline: 1.2452x; 1.2452x over previous
#include <cuda_runtime.h>
#include <math.h>

#define NDIM    64
#define LD      65            // padded row stride (floats) for A/V in smem
#define NMAT    4096
#define NDOMS   8
#define MATSZ   (NDIM*NDIM)   // 4096
#define BUF     (NDIM*LD)     // 4160 floats per smem matrix buffer
#define MAXSWEEPS 8
#define EIG_EPS 1e-4f
#define EPS_C   1e-5f
#define ETA_C   1.0f

// ---------------- device scratch (no allocations allowed) ----------------
__device__ float g_bmsum [NDOMS*MATSZ];
__device__ float g_bm_sq [NDOMS*MATSZ];
__device__ float g_bm_isq[NDOMS*MATSZ];
__device__ float g_GT    [NDOMS*MATSZ];
__device__ float g_rm_isq[NDOMS*MATSZ];
__device__ float g_Bsq   [MATSZ];
__device__ float g_sumsq [NDOMS];
__device__ float g_cnt   [NDOMS];
__device__ float g_s     [NDOMS];
__device__ int   g_noBsq;
__device__ float g_XT    [(size_t)NMAT*MATSZ];   // 64MB scratch for per-element tangent mats

// ---------------- helpers ----------------
__device__ __forceinline__ float blockReduceSum(float v) {
    __shared__ float red[8];
    const unsigned m = 0xffffffffu;
    #pragma unroll
    for (int o = 16; o; o >>= 1) v += __shfl_down_sync(m, v, o);
    if ((threadIdx.x & 31) == 0) red[threadIdx.x >> 5] = v;
    __syncthreads();
    if (threadIdx.x < 32) {
        float x = (threadIdx.x < 8) ? red[threadIdx.x] : 0.0f;
        #pragma unroll
        for (int o = 4; o; o >>= 1) x += __shfl_down_sync(m, x, o);
        if (threadIdx.x == 0) red[0] = x;
    }
    __syncthreads();
    float r = red[0];
    __syncthreads();
    return r;
}

// C(64x64) = A * B   (or A * B^T).  A,B in smem with stride LD.
// C may be smem (ldc=LD) or global row-major (ldc=64).
template<bool TRANSB>
__device__ __forceinline__ void mm64(const float* __restrict__ A,
                                     const float* __restrict__ B,
                                     float* __restrict__ C, int ldc) {
    const int tid = threadIdx.x;
    const int r0 = (tid >> 4) << 2;
    const int c0 = (tid & 15) << 2;
    float acc[4][4];
    #pragma unroll
    for (int i = 0; i < 4; i++)
        #pragma unroll
        for (int j = 0; j < 4; j++) acc[i][j] = 0.0f;
    #pragma unroll 4
    for (int k = 0; k < 64; k++) {
        float a0 = A[(r0+0)*LD + k];
        float a1 = A[(r0+1)*LD + k];
        float a2 = A[(r0+2)*LD + k];
        float a3 = A[(r0+3)*LD + k];
        float b0, b1, b2, b3;
        if (TRANSB) {
            b0 = B[(c0+0)*LD + k]; b1 = B[(c0+1)*LD + k];
            b2 = B[(c0+2)*LD + k]; b3 = B[(c0+3)*LD + k];
        } else {
            b0 = B[k*LD + c0+0]; b1 = B[k*LD + c0+1];
            b2 = B[k*LD + c0+2]; b3 = B[k*LD + c0+3];
        }
        acc[0][0] += a0*b0; acc[0][1] += a0*b1; acc[0][2] += a0*b2; acc[0][3] += a0*b3;
        acc[1][0] += a1*b0; acc[1][1] += a1*b1; acc[1][2] += a1*b2; acc[1][3] += a1*b3;
        acc[2][0] += a2*b0; acc[2][1] += a2*b1; acc[2][2] += a2*b2; acc[2][3] += a2*b3;
        acc[3][0] += a3*b0; acc[3][1] += a3*b1; acc[3][2] += a3*b2; acc[3][3] += a3*b3;
    }
    #pragma unroll
    for (int i = 0; i < 4; i++)
        #pragma unroll
        for (int j = 0; j < 4; j++)
            C[(size_t)(r0+i)*ldc + c0 + j] = acc[i][j];
}

__device__ __forceinline__ void symmetrize(const float* __restrict__ S, float* __restrict__ D) {
    for (int i = threadIdx.x; i < MATSZ; i += 256) {
        int r = i >> 6, c = i & 63;
        D[r*LD+c] = 0.5f*(S[r*LD+c] + S[c*LD+r]);
    }
}

// Block-parallel cyclic Jacobi with adaptive termination + per-rotation skipping.
// A (symmetric, smem, stride LD) diagonalized in place; V accumulates eigenvectors.
__device__ void jacobi_eig(float* A, float* V) {
    __shared__ float sc[32], ss[32];
    __shared__ int   spv[32], sqv[32];
    const int tid = threadIdx.x;
    for (int i = tid; i < MATSZ; i += 256) {
        int r = i >> 6, c = i & 63;
        V[r*LD+c] = (r == c) ? 1.0f : 0.0f;
    }
    __syncthreads();
    for (int sw = 0; sw < MAXSWEEPS; sw++) {
        for (int rd = 0; rd < 63; rd++) {
            if (tid < 32) {
                int x = (rd * 32) % 63;      // round-robin tournament pairing
                int p, q;
                if (tid == 0) { p = x; q = 63; }
                else {
                    int a = x + tid;      if (a >= 63) a -= 63;
                    int b = x - tid;      if (b < 0)   b += 63;
                    p = min(a, b); q = max(a, b);
                }
                spv[tid] = p; sqv[tid] = q;
                float apq = A[p*LD+q];
                float app = A[p*LD+p], aqq = A[q*LD+q];
                float c = 1.0f, s = 0.0f;
                // skip negligible rotations (below the convergence tolerance)
                if (fabsf(apq) > 1e-8f * (fabsf(app) + fabsf(aqq)) + 1e-30f) {
                    float tau = (aqq - app) / (2.0f * apq);
                    float t   = 1.0f / (fabsf(tau) + sqrtf(1.0f + tau*tau));
                    if (tau < 0.0f) t = -t;
                    c = 1.0f / sqrtf(1.0f + t*t);
                    s = t * c;
                }
                sc[tid] = c; ss[tid] = s;
            }
            __syncthreads();
            const int slot = tid >> 3;
            const int p = spv[slot], q = sqv[slot];
            const float c = sc[slot], s = ss[slot];
            const int k0 = tid & 7;
            if (s != 0.0f) {
                #pragma unroll
                for (int j = 0; j < 8; j++) {      // row phase: A <- J^T A
                    int k = k0 + 8*j;
                    float ap = A[p*LD+k], aq = A[q*LD+k];
                    A[p*LD+k] = c*ap - s*aq;
                    A[q*LD+k] = s*ap + c*aq;
                }
            }
            __syncthreads();
            if (s != 0.0f) {
                #pragma unroll
                for (int j = 0; j < 8; j++) {      // col phase: A <- A J ; V <- V J
                    int k = k0 + 8*j;
                    float ap = A[k*LD+p], aq = A[k*LD+q];
                    A[k*LD+p] = c*ap - s*aq;
                    A[k*LD+q] = s*ap + c*aq;
                    float vp = V[k*LD+p], vq = V[k*LD+q];
                    V[k*LD+p] = c*vp - s*vq;
                    V[k*LD+q] = s*vp + c*vq;
                }
            }
            __syncthreads();
        }
        // convergence check: exit when off-diagonal mass hits the fp32 floor
        float offs = 0.0f, tots = 0.0f;
        for (int i = tid; i < MATSZ; i += 256) {
            int r = i >> 6, c = i & 63;
            float a = A[r*LD+c];
            float a2 = a*a;
            tots += a2;
            if (r != c) offs += a2;
        }
        float offT = blockReduceSum(offs);
        float totT = blockReduceSum(tots);
        if (offT <= 1e-10f * totT + 1e-30f) break;
    }
}

// ---------------- kernels ----------------
__global__ void kzero_kernel() {
    int i = blockIdx.x * blockDim.x + threadIdx.x;
    int stride = gridDim.x * blockDim.x;
    for (int j = i; j < NDOMS*MATSZ; j += stride) { g_bmsum[j] = 0.0f; g_GT[j] = 0.0f; }
    if (i < NDOMS) g_sumsq[i] = 0.0f;
}

// per-domain sums of X  (bm numerator)
__global__ void __launch_bounds__(256) k1_kernel(const float* __restrict__ X,
                                                 const int* __restrict__ dd) {
    __shared__ int sdom[128];
    const int e  = blockIdx.x * 256 + threadIdx.x;
    const int n0 = blockIdx.y * 128;
    if (threadIdx.x < 128) sdom[threadIdx.x] = dd[n0 + threadIdx.x];
    __syncthreads();
    float acc[NDOMS];
    #pragma unroll
    for (int k = 0; k < NDOMS; k++) acc[k] = 0.0f;
    for (int m = 0; m < 128; m++) {
        float x = X[(size_t)(n0 + m) * MATSZ + e];
        int dom = sdom[m];
        #pragma unroll
        for (int k = 0; k < NDOMS; k++) acc[k] += (dom == k) ? x : 0.0f;
    }
    #pragma unroll
    for (int k = 0; k < NDOMS; k++) atomicAdd(&g_bmsum[k*MATSZ + e], acc[k]);
}

// per-domain: cnt, bm = sum/cnt, eig(bm) -> bm_sq, bm_isq
__global__ void __launch_bounds__(256) k2_kernel(const int* __restrict__ dd) {
    extern __shared__ float sm[];
    float* SX = sm;
    float* SA = sm + BUF;
    float* SV = sm + 2*BUF;
    __shared__ float sl[64];
    const int dom = blockIdx.x, tid = threadIdx.x;

    float loc = 0.0f;
    for (int i = tid; i < NMAT; i += 256) loc += (dd[i] == dom) ? 1.0f : 0.0f;
    float cnt  = blockReduceSum(loc);
    float cntf = fmaxf(cnt, 1.0f);
    if (tid == 0) g_cnt[dom] = cntf;

    for (int i = tid; i < MATSZ; i += 256) {
        int r = i >> 6, c = i & 63;
        SX[r*LD+c] = g_bmsum[dom*MATSZ + i] / cntf;
    }
    __syncthreads();
    symmetrize(SX, SA);
    __syncthreads();
    jacobi_eig(SA, SV);
    if (tid < 64) sl[tid] = fmaxf(SA[tid*LD+tid], EIG_EPS);
    __syncthreads();
    for (int i = tid; i < MATSZ; i += 256) {
        int r = i >> 6, c = i & 63;
        SX[r*LD+c] = SV[r*LD+c] * sqrtf(sl[c]);
    }
    __syncthreads();
    mm64<true>(SX, SV, g_bm_sq + dom*MATSZ, 64);
    __syncthreads();
    for (int i = tid; i < MATSZ; i += 256) {
        int r = i >> 6, c = i & 63;
        SX[r*LD+c] = SV[r*LD+c] / sqrtf(sl[c]);
    }
    __syncthreads();
    mm64<true>(SX, SV, g_bm_isq + dom*MATSZ, 64);
}

// per-element: XT = logm(bm_isq X bm_isq) -> g_XT ; sum||XT||^2 from eigenvalues
__global__ void __launch_bounds__(256) k3_kernel(const float* __restrict__ X,
                                                 const int* __restrict__ dd) {
    extern __shared__ float sm[];
    float* SX = sm;           float* SQ = sm + BUF;
    float* SA = sm + 2*BUF;   float* SV = sm + 3*BUF;
    __shared__ float sl[64];
    const int n = blockIdx.x, tid = threadIdx.x;
    const int dom = dd[n];
    const float* xg = X + (size_t)n * MATSZ;
    const float* qg = g_bm_isq + dom * MATSZ;
    for (int i = tid; i < MATSZ; i += 256) {
        int r = i >> 6, c = i & 63;
        SX[r*LD+c] = xg[i];
        SQ[r*LD+c] = qg[i];
    }
    __syncthreads();
    mm64<false>(SQ, SX, SA, LD);   __syncthreads();   // T = Q X
    mm64<false>(SA, SQ, SV, LD);   __syncthreads();   // M = T Q
    symmetrize(SV, SA);            __syncthreads();
    jacobi_eig(SA, SV);
    float lv = 0.0f;
    if (tid < 64) { lv = logf(fmaxf(SA[tid*LD+tid], EIG_EPS)); sl[tid] = lv; }
    float sq = blockReduceSum(lv * lv);                // ||logm||_F^2 = sum log^2(lam)
    if (tid == 0) atomicAdd(&g_sumsq[dom], sq);
    for (int i = tid; i < MATSZ; i += 256) {
        int r = i >> 6, c = i & 63;
        SX[r*LD+c] = SV[r*LD+c] * sl[c];
    }
    __syncthreads();
    mm64<true>(SX, SV, g_XT + (size_t)n * MATSZ, 64);  // XT -> scratch (coalesced)
}

// domain sums of XT (replaces 16.7M element atomics with 1M chunked atomics)
__global__ void __launch_bounds__(256) k3b_kernel(const int* __restrict__ dd) {
    __shared__ int sdom[128];
    const int e  = blockIdx.x * 256 + threadIdx.x;
    const int n0 = blockIdx.y * 128;
    if (threadIdx.x < 128) sdom[threadIdx.x] = dd[n0 + threadIdx.x];
    __syncthreads();
    float acc[NDOMS];
    #pragma unroll
    for (int k = 0; k < NDOMS; k++) acc[k] = 0.0f;
    for (int m = 0; m < 128; m++) {
        float x = g_XT[(size_t)(n0 + m) * MATSZ + e];
        int dom = sdom[m];
        #pragma unroll
        for (int k = 0; k < NDOMS; k++) acc[k] += (dom == k) ? x : 0.0f;
    }
    #pragma unroll
    for (int k = 0; k < NDOMS; k++) atomicAdd(&g_GT[k*MATSZ + e], acc[k]);
}

// per-domain update: bm_new, rm, rm_isq, GT2, batch_var, s.  Block 8: B_sq = sqrtm(mean).
__global__ void __launch_bounds__(256) k4_kernel(const float* __restrict__ mean,
                                                 const float* __restrict__ stdv) {
    extern __shared__ float sm[];
    float* SA = sm;           float* SV = sm + BUF;
    float* SQ = sm + 2*BUF;   float* SX = sm + 3*BUF;
    float* SG = sm + 4*BUF;
    __shared__ float sl[64];
    const int tid = threadIdx.x, b = blockIdx.x;

    if (b == NDOMS) {  // B_sq = sqrtm(mean), plus identity detection
        float dev = 0.0f;
        for (int i = tid; i < MATSZ; i += 256) {
            int r = i >> 6, c = i & 63;
            float mv = mean[i];
            SX[r*LD+c] = mv;
            dev += fabsf(mv - ((r == c) ? 1.0f : 0.0f));
        }
        float devT = blockReduceSum(dev);
        if (tid == 0) g_noBsq = (devT < 1e-6f) ? 1 : 0;
        __syncthreads();
        symmetrize(SX, SA); __syncthreads();
        jacobi_eig(SA, SV);
        if (tid < 64) sl[tid] = sqrtf(fmaxf(SA[tid*LD+tid], EIG_EPS));
        __syncthreads();
        for (int i = tid; i < MATSZ; i += 256) { int r=i>>6,c=i&63; SX[r*LD+c] = SV[r*LD+c]*sl[c]; }
        __syncthreads();
        mm64<true>(SX, SV, g_Bsq, 64);
        return;
    }
    const int dom = b;
    const float cntf = g_cnt[dom];
    for (int i = tid; i < MATSZ; i += 256) { int r=i>>6,c=i&63; SG[r*LD+c] = g_GT[dom*MATSZ+i] / cntf; }
    __syncthreads();
    symmetrize(SG, SA); __syncthreads();
    jacobi_eig(SA, SV);                               // eig(GT)
    if (tid < 64) sl[tid] = expf(SA[tid*LD+tid]);
    __syncthreads();
    for (int i = tid; i < MATSZ; i += 256) { int r=i>>6,c=i&63; SX[r*LD+c] = SV[r*LD+c]*sl[c]; }
    __syncthreads();
    mm64<true>(SX, SV, SQ, LD); __syncthreads();      // E = expm(GT)
    for (int i = tid; i < MATSZ; i += 256) { int r=i>>6,c=i&63; SA[r*LD+c] = g_bm_sq[dom*MATSZ+i]; }
    __syncthreads();
    mm64<false>(SA, SQ, SX, LD); __syncthreads();     // bm_sq E
    mm64<false>(SX, SA, SV, LD); __syncthreads();     // bm_new -> SV
    symmetrize(SV, SA); __syncthreads();
    jacobi_eig(SA, SQ);                               // eig(bm_new), U in SQ
    if (tid < 64) sl[tid] = fmaxf(SA[tid*LD+tid], EIG_EPS);   // rm eigenvalues
    __syncthreads();
    for (int i = tid; i < MATSZ; i += 256) { int r=i>>6,c=i&63; SX[r*LD+c] = SQ[r*LD+c]*sl[c]; }
    __syncthreads();
    mm64<true>(SX, SQ, SV, LD); __syncthreads();      // rm -> SV
    for (int i = tid; i < MATSZ; i += 256) { int r=i>>6,c=i&63; SX[r*LD+c] = SQ[r*LD+c]/sqrtf(sl[c]); }
    __syncthreads();
    mm64<true>(SX, SQ, g_rm_isq + dom*MATSZ, 64); __syncthreads();   // rm_isq -> global
    for (int i = tid; i < MATSZ; i += 256) { int r=i>>6,c=i&63; SA[r*LD+c] = g_bm_isq[dom*MATSZ+i]; }
    __syncthreads();
    mm64<false>(SA, SV, SX, LD); __syncthreads();     // bm_isq rm
    mm64<false>(SX, SA, SV, LD); __syncthreads();     // T1 -> SV
    symmetrize(SV, SA); __syncthreads();
    jacobi_eig(SA, SQ);                               // eig(T1)
    if (tid < 64) sl[tid] = logf(fmaxf(SA[tid*LD+tid], EIG_EPS));
    __syncthreads();
    for (int i = tid; i < MATSZ; i += 256) { int r=i>>6,c=i&63; SX[r*LD+c] = SQ[r*LD+c]*sl[c]; }
    __syncthreads();
    mm64<true>(SX, SQ, SV, LD); __syncthreads();      // GT2 -> SV
    float l1 = 0.0f, l2 = 0.0f;
    for (int i = tid; i < MATSZ; i += 256) {
        int r = i >> 6, c = i & 63;
        float g2 = SV[r*LD+c], g = SG[r*LD+c];
        l1 += g * g2; l2 += g2 * g2;
    }
    float dt = blockReduceSum(l1);
    float n2 = blockReduceSum(l2);
    if (tid == 0) {
        float var = g_sumsq[dom] / cntf - 2.0f * dt + n2;   // exact expansion
        float rv  = (1.0f - ETA_C) * 1.0f + ETA_C * var;
        g_s[dom]  = stdv[0] / sqrtf(rv + EPS_C);
    }
}

// per-element: Xn = B_sq * (rm_isq X rm_isq)^s * B_sq   (B_sq sandwich skipped if mean==I)
__global__ void __launch_bounds__(256) k5_kernel(const float* __restrict__ X,
                                                 const int* __restrict__ dd,
                                                 float* __restrict__ out) {
    extern __shared__ float sm[];
    float* SX = sm;           float* SQ = sm + BUF;
    float* SA = sm + 2*BUF;   float* SV = sm + 3*BUF;
    __shared__ float sl[64];
    const int n = blockIdx.x, tid = threadIdx.x;
    const int dom = dd[n];
    const int noB = g_noBsq;
    const float* xg = X + (size_t)n * MATSZ;
    const float* qg = g_rm_isq + dom * MATSZ;
    for (int i = tid; i < MATSZ; i += 256) {
        int r = i >> 6, c = i & 63;
        SX[r*LD+c] = xg[i];
        SQ[r*LD+c] = qg[i];
    }
    __syncthreads();
    mm64<false>(SQ, SX, SA, LD);   __syncthreads();
    mm64<false>(SA, SQ, SV, LD);   __syncthreads();
    symmetrize(SV, SA);            __syncthreads();
    jacobi_eig(SA, SV);
    const float sgl = g_s[dom];
    if (tid < 64) sl[tid] = expf(sgl * logf(fmaxf(SA[tid*LD+tid], EIG_EPS)));
    __syncthreads();
    for (int i = tid; i < MATSZ; i += 256) {
        int r = i >> 6, c = i & 63;
        SX[r*LD+c] = SV[r*LD+c] * sl[c];
    }
    __syncthreads();
    if (noB) {
        mm64<true>(SX, SV, out + (size_t)n * MATSZ, 64);   // Xn = P directly
    } else {
        mm64<true>(SX, SV, SQ, LD);    __syncthreads();    // P = expm(s * inner)
        for (int i = tid; i < MATSZ; i += 256) { int r=i>>6,c=i&63; SA[r*LD+c] = g_Bsq[i]; }
        __syncthreads();
        mm64<false>(SA, SQ, SV, LD);   __syncthreads();    // B_sq P
        mm64<false>(SV, SA, out + (size_t)n * MATSZ, 64);  // Xn
    }
}

// ---------------- launch ----------------
extern "C" void kernel_launch(void* const* d_in, const int* in_sizes, int n_in,
                              void* d_out, int out_size) {
    const float* X    = (const float*)d_in[0];
    const int*   dd   = (const int*)  d_in[1];
    const float* mean = (const float*)d_in[2];
    const float* stdv = (const float*)d_in[3];
    float* out = (float*)d_out;

    const int SM4 = 4 * BUF * (int)sizeof(float);
    const int SM5 = 5 * BUF * (int)sizeof(float);
    cudaFuncSetAttribute(k2_kernel, cudaFuncAttributeMaxDynamicSharedMemorySize, SM4);
    cudaFuncSetAttribute(k3_kernel, cudaFuncAttributeMaxDynamicSharedMemorySize, SM4);
    cudaFuncSetAttribute(k4_kernel, cudaFuncAttributeMaxDynamicSharedMemorySize, SM5);
    cudaFuncSetAttribute(k5_kernel, cudaFuncAttributeMaxDynamicSharedMemorySize, SM4);

    kzero_kernel<<<128, 256>>>();
    k1_kernel<<<dim3(16, 32), 256>>>(X, dd);
    k2_kernel<<<NDOMS, 256, SM4>>>(dd);
    k3_kernel<<<NMAT, 256, SM4>>>(X, dd);
    k3b_kernel<<<dim3(16, 32), 256>>>(dd);
    k4_kernel<<<NDOMS + 1, 256, SM5>>>(mean, stdv);
    k5_kernel<<<NMAT, 256, SM4>>>(X, dd, out);
}

// round 6
// speedup vs baseline: 2.3254x; 1.8674x over previous
#include <cuda_runtime.h>
#include <math.h>

#define NDIM    64
#define LD      65            // padded row stride: conflict-free for BOTH row & col access
#define NMAT    4096
#define NDOMS   8
#define MATSZ   (NDIM*NDIM)
#define BUF     (NDIM*LD)
#define MAXSWEEPS 8
#define EIG_EPS 1e-4f
#define EPS_C   1e-5f
#define ETA_C   1.0f

// ---------------- device scratch ----------------
__device__ float g_bmsum [NDOMS*MATSZ];
__device__ float g_bm_sq [NDOMS*MATSZ];
__device__ float g_bm_isq[NDOMS*MATSZ];
__device__ float g_GT    [NDOMS*MATSZ];
__device__ float g_rm_isq[NDOMS*MATSZ];
__device__ float g_Bsq   [MATSZ];
__device__ float g_sumsq [NDOMS];
__device__ float g_cnt   [NDOMS];
__device__ float g_s     [NDOMS];
__device__ int   g_noBsq;
__device__ float g_XT    [(size_t)NMAT*MATSZ];

// ---------------- helpers ----------------
__device__ __forceinline__ float blockReduceSum(float v) {
    __shared__ float red[8];
    const unsigned m = 0xffffffffu;
    #pragma unroll
    for (int o = 16; o; o >>= 1) v += __shfl_down_sync(m, v, o);
    if ((threadIdx.x & 31) == 0) red[threadIdx.x >> 5] = v;
    __syncthreads();
    if (threadIdx.x < 32) {
        float x = (threadIdx.x < 8) ? red[threadIdx.x] : 0.0f;
        #pragma unroll
        for (int o = 4; o; o >>= 1) x += __shfl_down_sync(m, x, o);
        if (threadIdx.x == 0) red[0] = x;
    }
    __syncthreads();
    float r = red[0];
    __syncthreads();
    return r;
}

template<bool TRANSB>
__device__ __forceinline__ void mm64(const float* __restrict__ A,
                                     const float* __restrict__ B,
                                     float* __restrict__ C, int ldc) {
    const int tid = threadIdx.x;
    const int r0 = (tid >> 4) << 2;
    const int c0 = (tid & 15) << 2;
    float acc[4][4];
    #pragma unroll
    for (int i = 0; i < 4; i++)
        #pragma unroll
        for (int j = 0; j < 4; j++) acc[i][j] = 0.0f;
    #pragma unroll 4
    for (int k = 0; k < 64; k++) {
        float a0 = A[(r0+0)*LD + k];
        float a1 = A[(r0+1)*LD + k];
        float a2 = A[(r0+2)*LD + k];
        float a3 = A[(r0+3)*LD + k];
        float b0, b1, b2, b3;
        if (TRANSB) {
            b0 = B[(c0+0)*LD + k]; b1 = B[(c0+1)*LD + k];
            b2 = B[(c0+2)*LD + k]; b3 = B[(c0+3)*LD + k];
        } else {
            b0 = B[k*LD + c0+0]; b1 = B[k*LD + c0+1];
            b2 = B[k*LD + c0+2]; b3 = B[k*LD + c0+3];
        }
        acc[0][0] += a0*b0; acc[0][1] += a0*b1; acc[0][2] += a0*b2; acc[0][3] += a0*b3;
        acc[1][0] += a1*b0; acc[1][1] += a1*b1; acc[1][2] += a1*b2; acc[1][3] += a1*b3;
        acc[2][0] += a2*b0; acc[2][1] += a2*b1; acc[2][2] += a2*b2; acc[2][3] += a2*b3;
        acc[3][0] += a3*b0; acc[3][1] += a3*b1; acc[3][2] += a3*b2; acc[3][3] += a3*b3;
    }
    #pragma unroll
    for (int i = 0; i < 4; i++)
        #pragma unroll
        for (int j = 0; j < 4; j++)
            C[(size_t)(r0+i)*ldc + c0 + j] = acc[i][j];
}

__device__ __forceinline__ void symmetrize(const float* __restrict__ S, float* __restrict__ D) {
    for (int i = threadIdx.x; i < MATSZ; i += 256) {
        int r = i >> 6, c = i & 63;
        D[r*LD+c] = 0.5f*(S[r*LD+c] + S[c*LD+r]);
    }
}

// Block-parallel cyclic Jacobi, conflict-free layout:
// 8 warps; each warp owns 4 rotation pairs per round. Lane l handles index l and l+32.
// Row access A[p*LD+l]: banks (p+l)%32 all distinct. Col access A[l*LD+p]: (l+p)%32 distinct.
// c,s per pair computed in-warp from broadcast LDS (no staging smem, 2 barriers/round).
__device__ void jacobi_eig(float* A, float* V) {
    const int tid  = threadIdx.x;
    const int warp = tid >> 5;
    const int lane = tid & 31;
    for (int i = tid; i < MATSZ; i += 256) {
        int r = i >> 6, c = i & 63;
        V[r*LD+c] = (r == c) ? 1.0f : 0.0f;
    }
    __syncthreads();
    for (int sw = 0; sw < MAXSWEEPS; sw++) {
        for (int rd = 0; rd < 63; rd++) {
            int   pp[4], qq[4];
            float cc[4], ssv[4];
            const int x = (rd * 32) % 63;          // tournament pairing
            // ---- compute c,s and apply ROW phase (pairs are index-disjoint) ----
            #pragma unroll
            for (int t = 0; t < 4; t++) {
                const int slot = warp * 4 + t;
                int p, q;
                if (slot == 0) { p = x; q = 63; }
                else {
                    int a = x + slot; if (a >= 63) a -= 63;
                    int b = x - slot; if (b < 0)   b += 63;
                    p = min(a, b); q = max(a, b);
                }
                pp[t] = p; qq[t] = q;
                const float apq = A[p*LD+q];       // broadcast loads
                const float app = A[p*LD+p];
                const float aqq = A[q*LD+q];
                float c = 1.0f, s = 0.0f;
                if (fabsf(apq) > 1e-8f * (fabsf(app) + fabsf(aqq)) + 1e-30f) {
                    const float tau = (aqq - app) / (2.0f * apq);
                    float tt = 1.0f / (fabsf(tau) + sqrtf(1.0f + tau*tau));
                    if (tau < 0.0f) tt = -tt;
                    c = rsqrtf(1.0f + tt*tt);
                    s = tt * c;
                }
                cc[t] = c; ssv[t] = s;
                if (s != 0.0f) {
                    #pragma unroll
                    for (int kk = 0; kk < 2; kk++) {
                        const int k = lane + 32*kk;
                        const float ap = A[p*LD+k], aq = A[q*LD+k];
                        A[p*LD+k] = c*ap - s*aq;
                        A[q*LD+k] = s*ap + c*aq;
                    }
                }
            }
            __syncthreads();
            // ---- COL phase: A and V ----
            #pragma unroll
            for (int t = 0; t < 4; t++) {
                const float c = cc[t], s = ssv[t];
                if (s != 0.0f) {
                    const int p = pp[t], q = qq[t];
                    #pragma unroll
                    for (int kk = 0; kk < 2; kk++) {
                        const int r = lane + 32*kk;
                        const float ap = A[r*LD+p], aq = A[r*LD+q];
                        A[r*LD+p] = c*ap - s*aq;
                        A[r*LD+q] = s*ap + c*aq;
                        const float vp = V[r*LD+p], vq = V[r*LD+q];
                        V[r*LD+p] = c*vp - s*vq;
                        V[r*LD+q] = s*vp + c*vq;
                    }
                }
            }
            __syncthreads();
        }
        // convergence: exit when off-diagonal mass is negligible
        float offs = 0.0f, tots = 0.0f;
        for (int i = tid; i < MATSZ; i += 256) {
            int r = i >> 6, c = i & 63;
            float a = A[r*LD+c];
            float a2 = a*a;
            tots += a2;
            if (r != c) offs += a2;
        }
        float offT = blockReduceSum(offs);
        float totT = blockReduceSum(tots);
        if (offT <= 1e-9f * totT + 1e-30f) break;
    }
}

// ---------------- kernels ----------------
__global__ void kzero_kernel() {
    int i = blockIdx.x * blockDim.x + threadIdx.x;
    int stride = gridDim.x * blockDim.x;
    for (int j = i; j < NDOMS*MATSZ; j += stride) { g_bmsum[j] = 0.0f; g_GT[j] = 0.0f; }
    if (i < NDOMS) g_sumsq[i] = 0.0f;
}

__global__ void __launch_bounds__(256) k1_kernel(const float* __restrict__ X,
                                                 const int* __restrict__ dd) {
    __shared__ int sdom[128];
    const int e  = blockIdx.x * 256 + threadIdx.x;
    const int n0 = blockIdx.y * 128;
    if (threadIdx.x < 128) sdom[threadIdx.x] = dd[n0 + threadIdx.x];
    __syncthreads();
    float acc[NDOMS];
    #pragma unroll
    for (int k = 0; k < NDOMS; k++) acc[k] = 0.0f;
    for (int m = 0; m < 128; m++) {
        float x = X[(size_t)(n0 + m) * MATSZ + e];
        int dom = sdom[m];
        #pragma unroll
        for (int k = 0; k < NDOMS; k++) acc[k] += (dom == k) ? x : 0.0f;
    }
    #pragma unroll
    for (int k = 0; k < NDOMS; k++) atomicAdd(&g_bmsum[k*MATSZ + e], acc[k]);
}

__global__ void __launch_bounds__(256) k2_kernel(const int* __restrict__ dd) {
    extern __shared__ float sm[];
    float* SX = sm;
    float* SA = sm + BUF;
    float* SV = sm + 2*BUF;
    __shared__ float sl[64];
    const int dom = blockIdx.x, tid = threadIdx.x;

    float loc = 0.0f;
    for (int i = tid; i < NMAT; i += 256) loc += (dd[i] == dom) ? 1.0f : 0.0f;
    float cnt  = blockReduceSum(loc);
    float cntf = fmaxf(cnt, 1.0f);
    if (tid == 0) g_cnt[dom] = cntf;

    for (int i = tid; i < MATSZ; i += 256) {
        int r = i >> 6, c = i & 63;
        SX[r*LD+c] = g_bmsum[dom*MATSZ + i] / cntf;
    }
    __syncthreads();
    symmetrize(SX, SA);
    __syncthreads();
    jacobi_eig(SA, SV);
    if (tid < 64) sl[tid] = fmaxf(SA[tid*LD+tid], EIG_EPS);
    __syncthreads();
    for (int i = tid; i < MATSZ; i += 256) {
        int r = i >> 6, c = i & 63;
        SX[r*LD+c] = SV[r*LD+c] * sqrtf(sl[c]);
    }
    __syncthreads();
    mm64<true>(SX, SV, g_bm_sq + dom*MATSZ, 64);
    __syncthreads();
    for (int i = tid; i < MATSZ; i += 256) {
        int r = i >> 6, c = i & 63;
        SX[r*LD+c] = SV[r*LD+c] / sqrtf(sl[c]);
    }
    __syncthreads();
    mm64<true>(SX, SV, g_bm_isq + dom*MATSZ, 64);
}

__global__ void __launch_bounds__(256) k3_kernel(const float* __restrict__ X,
                                                 const int* __restrict__ dd) {
    extern __shared__ float sm[];
    float* SX = sm;           float* SQ = sm + BUF;
    float* SA = sm + 2*BUF;   float* SV = sm + 3*BUF;
    __shared__ float sl[64];
    const int n = blockIdx.x, tid = threadIdx.x;
    const int dom = dd[n];
    const float* xg = X + (size_t)n * MATSZ;
    const float* qg = g_bm_isq + dom * MATSZ;
    for (int i = tid; i < MATSZ; i += 256) {
        int r = i >> 6, c = i & 63;
        SX[r*LD+c] = xg[i];
        SQ[r*LD+c] = qg[i];
    }
    __syncthreads();
    mm64<false>(SQ, SX, SA, LD);   __syncthreads();
    mm64<false>(SA, SQ, SV, LD);   __syncthreads();
    symmetrize(SV, SA);            __syncthreads();
    jacobi_eig(SA, SV);
    float lv = 0.0f;
    if (tid < 64) { lv = logf(fmaxf(SA[tid*LD+tid], EIG_EPS)); sl[tid] = lv; }
    float sq = blockReduceSum(lv * lv);
    if (tid == 0) atomicAdd(&g_sumsq[dom], sq);
    for (int i = tid; i < MATSZ; i += 256) {
        int r = i >> 6, c = i & 63;
        SX[r*LD+c] = SV[r*LD+c] * sl[c];
    }
    __syncthreads();
    mm64<true>(SX, SV, g_XT + (size_t)n * MATSZ, 64);
}

__global__ void __launch_bounds__(256) k3b_kernel(const int* __restrict__ dd) {
    __shared__ int sdom[128];
    const int e  = blockIdx.x * 256 + threadIdx.x;
    const int n0 = blockIdx.y * 128;
    if (threadIdx.x < 128) sdom[threadIdx.x] = dd[n0 + threadIdx.x];
    __syncthreads();
    float acc[NDOMS];
    #pragma unroll
    for (int k = 0; k < NDOMS; k++) acc[k] = 0.0f;
    for (int m = 0; m < 128; m++) {
        float x = g_XT[(size_t)(n0 + m) * MATSZ + e];
        int dom = sdom[m];
        #pragma unroll
        for (int k = 0; k < NDOMS; k++) acc[k] += (dom == k) ? x : 0.0f;
    }
    #pragma unroll
    for (int k = 0; k < NDOMS; k++) atomicAdd(&g_GT[k*MATSZ + e], acc[k]);
}

__global__ void __launch_bounds__(256) k4_kernel(const float* __restrict__ mean,
                                                 const float* __restrict__ stdv) {
    extern __shared__ float sm[];
    float* SA = sm;           float* SV = sm + BUF;
    float* SQ = sm + 2*BUF;   float* SX = sm + 3*BUF;
    float* SG = sm + 4*BUF;
    __shared__ float sl[64];
    const int tid = threadIdx.x, b = blockIdx.x;

    if (b == NDOMS) {
        float dev = 0.0f;
        for (int i = tid; i < MATSZ; i += 256) {
            int r = i >> 6, c = i & 63;
            float mv = mean[i];
            SX[r*LD+c] = mv;
            dev += fabsf(mv - ((r == c) ? 1.0f : 0.0f));
        }
        float devT = blockReduceSum(dev);
        if (tid == 0) g_noBsq = (devT < 1e-6f) ? 1 : 0;
        __syncthreads();
        symmetrize(SX, SA); __syncthreads();
        jacobi_eig(SA, SV);
        if (tid < 64) sl[tid] = sqrtf(fmaxf(SA[tid*LD+tid], EIG_EPS));
        __syncthreads();
        for (int i = tid; i < MATSZ; i += 256) { int r=i>>6,c=i&63; SX[r*LD+c] = SV[r*LD+c]*sl[c]; }
        __syncthreads();
        mm64<true>(SX, SV, g_Bsq, 64);
        return;
    }
    const int dom = b;
    const float cntf = g_cnt[dom];
    for (int i = tid; i < MATSZ; i += 256) { int r=i>>6,c=i&63; SG[r*LD+c] = g_GT[dom*MATSZ+i] / cntf; }
    __syncthreads();
    symmetrize(SG, SA); __syncthreads();
    jacobi_eig(SA, SV);
    if (tid < 64) sl[tid] = expf(SA[tid*LD+tid]);
    __syncthreads();
    for (int i = tid; i < MATSZ; i += 256) { int r=i>>6,c=i&63; SX[r*LD+c] = SV[r*LD+c]*sl[c]; }
    __syncthreads();
    mm64<true>(SX, SV, SQ, LD); __syncthreads();
    for (int i = tid; i < MATSZ; i += 256) { int r=i>>6,c=i&63; SA[r*LD+c] = g_bm_sq[dom*MATSZ+i]; }
    __syncthreads();
    mm64<false>(SA, SQ, SX, LD); __syncthreads();
    mm64<false>(SX, SA, SV, LD); __syncthreads();
    symmetrize(SV, SA); __syncthreads();
    jacobi_eig(SA, SQ);
    if (tid < 64) sl[tid] = fmaxf(SA[tid*LD+tid], EIG_EPS);
    __syncthreads();
    for (int i = tid; i < MATSZ; i += 256) { int r=i>>6,c=i&63; SX[r*LD+c] = SQ[r*LD+c]*sl[c]; }
    __syncthreads();
    mm64<true>(SX, SQ, SV, LD); __syncthreads();
    for (int i = tid; i < MATSZ; i += 256) { int r=i>>6,c=i&63; SX[r*LD+c] = SQ[r*LD+c]/sqrtf(sl[c]); }
    __syncthreads();
    mm64<true>(SX, SQ, g_rm_isq + dom*MATSZ, 64); __syncthreads();
    for (int i = tid; i < MATSZ; i += 256) { int r=i>>6,c=i&63; SA[r*LD+c] = g_bm_isq[dom*MATSZ+i]; }
    __syncthreads();
    mm64<false>(SA, SV, SX, LD); __syncthreads();
    mm64<false>(SX, SA, SV, LD); __syncthreads();
    symmetrize(SV, SA); __syncthreads();
    jacobi_eig(SA, SQ);
    if (tid < 64) sl[tid] = logf(fmaxf(SA[tid*LD+tid], EIG_EPS));
    __syncthreads();
    for (int i = tid; i < MATSZ; i += 256) { int r=i>>6,c=i&63; SX[r*LD+c] = SQ[r*LD+c]*sl[c]; }
    __syncthreads();
    mm64<true>(SX, SQ, SV, LD); __syncthreads();
    float l1 = 0.0f, l2 = 0.0f;
    for (int i = tid; i < MATSZ; i += 256) {
        int r = i >> 6, c = i & 63;
        float g2 = SV[r*LD+c], g = SG[r*LD+c];
        l1 += g * g2; l2 += g2 * g2;
    }
    float dt = blockReduceSum(l1);
    float n2 = blockReduceSum(l2);
    if (tid == 0) {
        float var = g_sumsq[dom] / cntf - 2.0f * dt + n2;
        float rv  = (1.0f - ETA_C) * 1.0f + ETA_C * var;
        g_s[dom]  = stdv[0] / sqrtf(rv + EPS_C);
    }
}

__global__ void __launch_bounds__(256) k5_kernel(const float* __restrict__ X,
                                                 const int* __restrict__ dd,
                                                 float* __restrict__ out) {
    extern __shared__ float sm[];
    float* SX = sm;           float* SQ = sm + BUF;
    float* SA = sm + 2*BUF;   float* SV = sm + 3*BUF;
    __shared__ float sl[64];
    const int n = blockIdx.x, tid = threadIdx.x;
    const int dom = dd[n];
    const int noB = g_noBsq;
    const float* xg = X + (size_t)n * MATSZ;
    const float* qg = g_rm_isq + dom * MATSZ;
    for (int i = tid; i < MATSZ; i += 256) {
        int r = i >> 6, c = i & 63;
        SX[r*LD+c] = xg[i];
        SQ[r*LD+c] = qg[i];
    }
    __syncthreads();
    mm64<false>(SQ, SX, SA, LD);   __syncthreads();
    mm64<false>(SA, SQ, SV, LD);   __syncthreads();
    symmetrize(SV, SA);            __syncthreads();
    jacobi_eig(SA, SV);
    const float sgl = g_s[dom];
    if (tid < 64) sl[tid] = expf(sgl * logf(fmaxf(SA[tid*LD+tid], EIG_EPS)));
    __syncthreads();
    for (int i = tid; i < MATSZ; i += 256) {
        int r = i >> 6, c = i & 63;
        SX[r*LD+c] = SV[r*LD+c] * sl[c];
    }
    __syncthreads();
    if (noB) {
        mm64<true>(SX, SV, out + (size_t)n * MATSZ, 64);
    } else {
        mm64<true>(SX, SV, SQ, LD);    __syncthreads();
        for (int i = tid; i < MATSZ; i += 256) { int r=i>>6,c=i&63; SA[r*LD+c] = g_Bsq[i]; }
        __syncthreads();
        mm64<false>(SA, SQ, SV, LD);   __syncthreads();
        mm64<false>(SV, SA, out + (size_t)n * MATSZ, 64);
    }
}

// ---------------- launch ----------------
extern "C" void kernel_launch(void* const* d_in, const int* in_sizes, int n_in,
                              void* d_out, int out_size) {
    const float* X    = (const float*)d_in[0];
    const int*   dd   = (const int*)  d_in[1];
    const float* mean = (const float*)d_in[2];
    const float* stdv = (const float*)d_in[3];
    float* out = (float*)d_out;

    const int SM4 = 4 * BUF * (int)sizeof(float);
    const int SM5 = 5 * BUF * (int)sizeof(float);
    cudaFuncSetAttribute(k2_kernel, cudaFuncAttributeMaxDynamicSharedMemorySize, SM4);
    cudaFuncSetAttribute(k3_kernel, cudaFuncAttributeMaxDynamicSharedMemorySize, SM4);
    cudaFuncSetAttribute(k4_kernel, cudaFuncAttributeMaxDynamicSharedMemorySize, SM5);
    cudaFuncSetAttribute(k5_kernel, cudaFuncAttributeMaxDynamicSharedMemorySize, SM4);

    kzero_kernel<<<128, 256>>>();
    k1_kernel<<<dim3(16, 32), 256>>>(X, dd);
    k2_kernel<<<NDOMS, 256, SM4>>>(dd);
    k3_kernel<<<NMAT, 256, SM4>>>(X, dd);
    k3b_kernel<<<dim3(16, 32), 256>>>(dd);
    k4_kernel<<<NDOMS + 1, 256, SM5>>>(mean, stdv);
    k5_kernel<<<NMAT, 256, SM4>>>(X, dd, out);
}

// round 7
// speedup vs baseline: 3.3001x; 1.4192x over previous
#include <cuda_runtime.h>
#include <math.h>

#define NDIM    64
#define LD      65            // conflict-free for both row & col access patterns
#define NMAT    4096
#define NDOMS   8
#define MATSZ   (NDIM*NDIM)
#define BUF     (NDIM*LD)
#define MAXSWEEPS 8
#define EIG_EPS 1e-4f
#define EPS_C   1e-5f
#define ETA_C   1.0f

// ---------------- device scratch ----------------
__device__ float g_bmsum [NDOMS*MATSZ];
__device__ float g_bm_sq [NDOMS*MATSZ];
__device__ float g_bm_isq[NDOMS*MATSZ];
__device__ float g_GT    [NDOMS*MATSZ];
__device__ float g_rm_isq[NDOMS*MATSZ];
__device__ float g_Bsq   [MATSZ];
__device__ float g_sumsq [NDOMS];
__device__ float g_cnt   [NDOMS];
__device__ float g_s     [NDOMS];
__device__ int   g_noBsq;
__device__ float g_XT    [(size_t)NMAT*MATSZ];

// ---------------- helpers ----------------
__device__ __forceinline__ float blockReduceSum(float v) {
    __shared__ float red[8];
    const unsigned m = 0xffffffffu;
    #pragma unroll
    for (int o = 16; o; o >>= 1) v += __shfl_down_sync(m, v, o);
    if ((threadIdx.x & 31) == 0) red[threadIdx.x >> 5] = v;
    __syncthreads();
    if (threadIdx.x < 32) {
        float x = (threadIdx.x < 8) ? red[threadIdx.x] : 0.0f;
        #pragma unroll
        for (int o = 4; o; o >>= 1) x += __shfl_down_sync(m, x, o);
        if (threadIdx.x == 0) red[0] = x;
    }
    __syncthreads();
    float r = red[0];
    __syncthreads();
    return r;
}

template<bool TRANSB>
__device__ __forceinline__ void mm64(const float* __restrict__ A,
                                     const float* __restrict__ B,
                                     float* __restrict__ C, int ldc) {
    const int tid = threadIdx.x;
    const int r0 = (tid >> 4) << 2;
    const int c0 = (tid & 15) << 2;
    float acc[4][4];
    #pragma unroll
    for (int i = 0; i < 4; i++)
        #pragma unroll
        for (int j = 0; j < 4; j++) acc[i][j] = 0.0f;
    #pragma unroll 4
    for (int k = 0; k < 64; k++) {
        float a0 = A[(r0+0)*LD + k];
        float a1 = A[(r0+1)*LD + k];
        float a2 = A[(r0+2)*LD + k];
        float a3 = A[(r0+3)*LD + k];
        float b0, b1, b2, b3;
        if (TRANSB) {
            b0 = B[(c0+0)*LD + k]; b1 = B[(c0+1)*LD + k];
            b2 = B[(c0+2)*LD + k]; b3 = B[(c0+3)*LD + k];
        } else {
            b0 = B[k*LD + c0+0]; b1 = B[k*LD + c0+1];
            b2 = B[k*LD + c0+2]; b3 = B[k*LD + c0+3];
        }
        acc[0][0] += a0*b0; acc[0][1] += a0*b1; acc[0][2] += a0*b2; acc[0][3] += a0*b3;
        acc[1][0] += a1*b0; acc[1][1] += a1*b1; acc[1][2] += a1*b2; acc[1][3] += a1*b3;
        acc[2][0] += a2*b0; acc[2][1] += a2*b1; acc[2][2] += a2*b2; acc[2][3] += a2*b3;
        acc[3][0] += a3*b0; acc[3][1] += a3*b1; acc[3][2] += a3*b2; acc[3][3] += a3*b3;
    }
    #pragma unroll
    for (int i = 0; i < 4; i++)
        #pragma unroll
        for (int j = 0; j < 4; j++)
            C[(size_t)(r0+i)*ldc + c0 + j] = acc[i][j];
}

__device__ __forceinline__ void symmetrize(const float* __restrict__ S, float* __restrict__ D) {
    for (int i = threadIdx.x; i < MATSZ; i += 256) {
        int r = i >> 6, c = i & 63;
        D[r*LD+c] = 0.5f*(S[r*LD+c] + S[c*LD+r]);
    }
}

// Block-parallel cyclic Jacobi.
// - lanes 0..3 compute their pair's (p,q,c,s) in parallel (no 4x redundant sqrt chains),
//   broadcast via shfl.
// - row/col phases conflict-free under LD=65.
// - rotation skipping + adaptive sweep exit.
__device__ void jacobi_eig(float* A, float* V) {
    const int tid  = threadIdx.x;
    const int warp = tid >> 5;
    const int lane = tid & 31;
    const unsigned FULL = 0xffffffffu;
    for (int i = tid; i < MATSZ; i += 256) {
        int r = i >> 6, c = i & 63;
        V[r*LD+c] = (r == c) ? 1.0f : 0.0f;
    }
    __syncthreads();
    for (int sw = 0; sw < MAXSWEEPS; sw++) {
        for (int rd = 0; rd < 63; rd++) {
            const int x = (rd * 32) % 63;
            int myp = 0, myq = 0; float myc = 1.0f, mys = 0.0f;
            if (lane < 4) {
                const int slot = warp * 4 + lane;
                if (slot == 0) { myp = x; myq = 63; }
                else {
                    int a = x + slot; if (a >= 63) a -= 63;
                    int b = x - slot; if (b < 0)   b += 63;
                    myp = min(a, b); myq = max(a, b);
                }
                const float apq = A[myp*LD+myq];
                const float app = A[myp*LD+myp];
                const float aqq = A[myq*LD+myq];
                if (fabsf(apq) > 2e-7f * (fabsf(app) + fabsf(aqq))) {
                    const float tau = (aqq - app) / (2.0f * apq);
                    float t = 1.0f / (fabsf(tau) + sqrtf(1.0f + tau*tau));
                    if (tau < 0.0f) t = -t;
                    myc = rsqrtf(1.0f + t*t);
                    mys = t * myc;
                }
            }
            int pp[4], qq[4]; float cc[4], ssv[4];
            #pragma unroll
            for (int t = 0; t < 4; t++) {
                pp[t]  = __shfl_sync(FULL, myp, t);
                qq[t]  = __shfl_sync(FULL, myq, t);
                cc[t]  = __shfl_sync(FULL, myc, t);
                ssv[t] = __shfl_sync(FULL, mys, t);
            }
            // ---- ROW phase: A <- J^T A  (pairs row-disjoint) ----
            #pragma unroll
            for (int t = 0; t < 4; t++) {
                const float c = cc[t], s = ssv[t];
                if (s != 0.0f) {
                    float* Ap = A + pp[t]*LD;
                    float* Aq = A + qq[t]*LD;
                    #pragma unroll
                    for (int kk = 0; kk < 2; kk++) {
                        const int k = lane + 32*kk;
                        const float ap = Ap[k], aq = Aq[k];
                        Ap[k] = c*ap - s*aq;
                        Aq[k] = s*ap + c*aq;
                    }
                }
            }
            __syncthreads();
            // ---- COL phase: A <- A J ; V <- V J  (pairs col-disjoint) ----
            float* Ar0 = A + lane*LD;
            float* Vr0 = V + lane*LD;
            #pragma unroll
            for (int t = 0; t < 4; t++) {
                const float c = cc[t], s = ssv[t];
                if (s != 0.0f) {
                    const int p = pp[t], q = qq[t];
                    #pragma unroll
                    for (int kk = 0; kk < 2; kk++) {
                        float* Ar = Ar0 + 32*LD*kk;
                        float* Vr = Vr0 + 32*LD*kk;
                        const float ap = Ar[p], aq = Ar[q];
                        Ar[p] = c*ap - s*aq;
                        Ar[q] = s*ap + c*aq;
                        const float vp = Vr[p], vq = Vr[q];
                        Vr[p] = c*vp - s*vq;
                        Vr[q] = s*vp + c*vq;
                    }
                }
            }
            __syncthreads();
        }
        float offs = 0.0f, tots = 0.0f;
        for (int i = tid; i < MATSZ; i += 256) {
            int r = i >> 6, c = i & 63;
            float a = A[r*LD+c];
            float a2 = a*a;
            tots += a2;
            if (r != c) offs += a2;
        }
        float offT = blockReduceSum(offs);
        float totT = blockReduceSum(tots);
        if (offT <= 1e-8f * totT + 1e-30f) break;
    }
}

// ---------------- kernels ----------------
__global__ void kzero_kernel() {
    int i = blockIdx.x * blockDim.x + threadIdx.x;
    int stride = gridDim.x * blockDim.x;
    for (int j = i; j < NDOMS*MATSZ; j += stride) { g_bmsum[j] = 0.0f; g_GT[j] = 0.0f; }
    if (i < NDOMS) g_sumsq[i] = 0.0f;
}

__global__ void __launch_bounds__(256) k1_kernel(const float* __restrict__ X,
                                                 const int* __restrict__ dd) {
    __shared__ int sdom[128];
    const int e  = blockIdx.x * 256 + threadIdx.x;
    const int n0 = blockIdx.y * 128;
    if (threadIdx.x < 128) sdom[threadIdx.x] = dd[n0 + threadIdx.x];
    __syncthreads();
    float acc[NDOMS];
    #pragma unroll
    for (int k = 0; k < NDOMS; k++) acc[k] = 0.0f;
    for (int m = 0; m < 128; m++) {
        float x = X[(size_t)(n0 + m) * MATSZ + e];
        int dom = sdom[m];
        #pragma unroll
        for (int k = 0; k < NDOMS; k++) acc[k] += (dom == k) ? x : 0.0f;
    }
    #pragma unroll
    for (int k = 0; k < NDOMS; k++) atomicAdd(&g_bmsum[k*MATSZ + e], acc[k]);
}

__global__ void __launch_bounds__(256) k2_kernel(const int* __restrict__ dd) {
    extern __shared__ float sm[];
    float* SX = sm;
    float* SA = sm + BUF;
    float* SV = sm + 2*BUF;
    __shared__ float sl[64];
    const int dom = blockIdx.x, tid = threadIdx.x;

    float loc = 0.0f;
    for (int i = tid; i < NMAT; i += 256) loc += (dd[i] == dom) ? 1.0f : 0.0f;
    float cnt  = blockReduceSum(loc);
    float cntf = fmaxf(cnt, 1.0f);
    if (tid == 0) g_cnt[dom] = cntf;

    for (int i = tid; i < MATSZ; i += 256) {
        int r = i >> 6, c = i & 63;
        SX[r*LD+c] = g_bmsum[dom*MATSZ + i] / cntf;
    }
    __syncthreads();
    symmetrize(SX, SA);
    __syncthreads();
    jacobi_eig(SA, SV);
    if (tid < 64) sl[tid] = fmaxf(SA[tid*LD+tid], EIG_EPS);
    __syncthreads();
    for (int i = tid; i < MATSZ; i += 256) {
        int r = i >> 6, c = i & 63;
        SX[r*LD+c] = SV[r*LD+c] * sqrtf(sl[c]);
    }
    __syncthreads();
    mm64<true>(SX, SV, g_bm_sq + dom*MATSZ, 64);
    __syncthreads();
    for (int i = tid; i < MATSZ; i += 256) {
        int r = i >> 6, c = i & 63;
        SX[r*LD+c] = SV[r*LD+c] / sqrtf(sl[c]);
    }
    __syncthreads();
    mm64<true>(SX, SV, g_bm_isq + dom*MATSZ, 64);
}

// per-element: XT = logm(bm_isq X bm_isq) -> g_XT ; sum||XT||^2 via eigenvalues.
// 3 smem buffers (49.9KB) -> 4 blocks/SM.
__global__ void __launch_bounds__(256) k3_kernel(const float* __restrict__ X,
                                                 const int* __restrict__ dd) {
    extern __shared__ float sm[];
    float* S0 = sm; float* S1 = sm + BUF; float* S2 = sm + 2*BUF;
    __shared__ float sl[64];
    const int n = blockIdx.x, tid = threadIdx.x;
    const int dom = dd[n];
    const float* xg = X + (size_t)n * MATSZ;
    const float* qg = g_bm_isq + dom * MATSZ;
    for (int i = tid; i < MATSZ; i += 256) {
        int r = i >> 6, c = i & 63;
        S0[r*LD+c] = xg[i];
        S1[r*LD+c] = qg[i];
    }
    __syncthreads();
    mm64<false>(S1, S0, S2, LD);  __syncthreads();   // T = Q·X   (X in S0, Q in S1)
    mm64<false>(S2, S1, S0, LD);  __syncthreads();   // M = T·Q   (X dead -> S0)
    symmetrize(S0, S1);           __syncthreads();   // A = sym(M) (Q dead -> S1)
    jacobi_eig(S1, S2);                              // A=S1, V=S2 (T dead)
    float lv = 0.0f;
    if (tid < 64) { lv = logf(fmaxf(S1[tid*LD+tid], EIG_EPS)); sl[tid] = lv; }
    float sq = blockReduceSum(lv * lv);
    if (tid == 0) atomicAdd(&g_sumsq[dom], sq);
    for (int i = tid; i < MATSZ; i += 256) {
        int r = i >> 6, c = i & 63;
        S0[r*LD+c] = S2[r*LD+c] * sl[c];                // W = V*diag (M dead -> S0)
    }
    __syncthreads();
    mm64<true>(S0, S2, g_XT + (size_t)n * MATSZ, 64);   // XT = W·Vᵀ
}

__global__ void __launch_bounds__(256) k3b_kernel(const int* __restrict__ dd) {
    __shared__ int sdom[128];
    const int e  = blockIdx.x * 256 + threadIdx.x;
    const int n0 = blockIdx.y * 128;
    if (threadIdx.x < 128) sdom[threadIdx.x] = dd[n0 + threadIdx.x];
    __syncthreads();
    float acc[NDOMS];
    #pragma unroll
    for (int k = 0; k < NDOMS; k++) acc[k] = 0.0f;
    for (int m = 0; m < 128; m++) {
        float x = g_XT[(size_t)(n0 + m) * MATSZ + e];
        int dom = sdom[m];
        #pragma unroll
        for (int k = 0; k < NDOMS; k++) acc[k] += (dom == k) ? x : 0.0f;
    }
    #pragma unroll
    for (int k = 0; k < NDOMS; k++) atomicAdd(&g_GT[k*MATSZ + e], acc[k]);
}

__global__ void __launch_bounds__(256) k4_kernel(const float* __restrict__ mean,
                                                 const float* __restrict__ stdv) {
    extern __shared__ float sm[];
    float* SA = sm;           float* SV = sm + BUF;
    float* SQ = sm + 2*BUF;   float* SX = sm + 3*BUF;
    float* SG = sm + 4*BUF;
    __shared__ float sl[64];
    const int tid = threadIdx.x, b = blockIdx.x;

    if (b == NDOMS) {
        float dev = 0.0f;
        for (int i = tid; i < MATSZ; i += 256) {
            int r = i >> 6, c = i & 63;
            float mv = mean[i];
            SX[r*LD+c] = mv;
            dev += fabsf(mv - ((r == c) ? 1.0f : 0.0f));
        }
        float devT = blockReduceSum(dev);
        if (tid == 0) g_noBsq = (devT < 1e-6f) ? 1 : 0;
        __syncthreads();
        symmetrize(SX, SA); __syncthreads();
        jacobi_eig(SA, SV);
        if (tid < 64) sl[tid] = sqrtf(fmaxf(SA[tid*LD+tid], EIG_EPS));
        __syncthreads();
        for (int i = tid; i < MATSZ; i += 256) { int r=i>>6,c=i&63; SX[r*LD+c] = SV[r*LD+c]*sl[c]; }
        __syncthreads();
        mm64<true>(SX, SV, g_Bsq, 64);
        return;
    }
    const int dom = b;
    const float cntf = g_cnt[dom];
    for (int i = tid; i < MATSZ; i += 256) { int r=i>>6,c=i&63; SG[r*LD+c] = g_GT[dom*MATSZ+i] / cntf; }
    __syncthreads();
    symmetrize(SG, SA); __syncthreads();
    jacobi_eig(SA, SV);
    if (tid < 64) sl[tid] = expf(SA[tid*LD+tid]);
    __syncthreads();
    for (int i = tid; i < MATSZ; i += 256) { int r=i>>6,c=i&63; SX[r*LD+c] = SV[r*LD+c]*sl[c]; }
    __syncthreads();
    mm64<true>(SX, SV, SQ, LD); __syncthreads();
    for (int i = tid; i < MATSZ; i += 256) { int r=i>>6,c=i&63; SA[r*LD+c] = g_bm_sq[dom*MATSZ+i]; }
    __syncthreads();
    mm64<false>(SA, SQ, SX, LD); __syncthreads();
    mm64<false>(SX, SA, SV, LD); __syncthreads();
    symmetrize(SV, SA); __syncthreads();
    jacobi_eig(SA, SQ);
    if (tid < 64) sl[tid] = fmaxf(SA[tid*LD+tid], EIG_EPS);
    __syncthreads();
    for (int i = tid; i < MATSZ; i += 256) { int r=i>>6,c=i&63; SX[r*LD+c] = SQ[r*LD+c]*sl[c]; }
    __syncthreads();
    mm64<true>(SX, SQ, SV, LD); __syncthreads();
    for (int i = tid; i < MATSZ; i += 256) { int r=i>>6,c=i&63; SX[r*LD+c] = SQ[r*LD+c]/sqrtf(sl[c]); }
    __syncthreads();
    mm64<true>(SX, SQ, g_rm_isq + dom*MATSZ, 64); __syncthreads();
    for (int i = tid; i < MATSZ; i += 256) { int r=i>>6,c=i&63; SA[r*LD+c] = g_bm_isq[dom*MATSZ+i]; }
    __syncthreads();
    mm64<false>(SA, SV, SX, LD); __syncthreads();
    mm64<false>(SX, SA, SV, LD); __syncthreads();
    symmetrize(SV, SA); __syncthreads();
    jacobi_eig(SA, SQ);
    if (tid < 64) sl[tid] = logf(fmaxf(SA[tid*LD+tid], EIG_EPS));
    __syncthreads();
    for (int i = tid; i < MATSZ; i += 256) { int r=i>>6,c=i&63; SX[r*LD+c] = SQ[r*LD+c]*sl[c]; }
    __syncthreads();
    mm64<true>(SX, SQ, SV, LD); __syncthreads();
    float l1 = 0.0f, l2 = 0.0f;
    for (int i = tid; i < MATSZ; i += 256) {
        int r = i >> 6, c = i & 63;
        float g2 = SV[r*LD+c], g = SG[r*LD+c];
        l1 += g * g2; l2 += g2 * g2;
    }
    float dt = blockReduceSum(l1);
    float n2 = blockReduceSum(l2);
    if (tid == 0) {
        float var = g_sumsq[dom] / cntf - 2.0f * dt + n2;
        float rv  = (1.0f - ETA_C) * 1.0f + ETA_C * var;
        g_s[dom]  = stdv[0] / sqrtf(rv + EPS_C);
    }
}

// per-element normalize. 3 smem buffers -> 4 blocks/SM.
__global__ void __launch_bounds__(256) k5_kernel(const float* __restrict__ X,
                                                 const int* __restrict__ dd,
                                                 float* __restrict__ out) {
    extern __shared__ float sm[];
    float* S0 = sm; float* S1 = sm + BUF; float* S2 = sm + 2*BUF;
    __shared__ float sl[64];
    const int n = blockIdx.x, tid = threadIdx.x;
    const int dom = dd[n];
    const int noB = g_noBsq;
    const float* xg = X + (size_t)n * MATSZ;
    const float* qg = g_rm_isq + dom * MATSZ;
    for (int i = tid; i < MATSZ; i += 256) {
        int r = i >> 6, c = i & 63;
        S0[r*LD+c] = xg[i];
        S1[r*LD+c] = qg[i];
    }
    __syncthreads();
    mm64<false>(S1, S0, S2, LD);  __syncthreads();   // T = Q·X
    mm64<false>(S2, S1, S0, LD);  __syncthreads();   // M = T·Q
    symmetrize(S0, S1);           __syncthreads();   // A -> S1
    jacobi_eig(S1, S2);                              // V -> S2
    const float sgl = g_s[dom];
    if (tid < 64) sl[tid] = expf(sgl * logf(fmaxf(S1[tid*LD+tid], EIG_EPS)));
    __syncthreads();
    for (int i = tid; i < MATSZ; i += 256) {
        int r = i >> 6, c = i & 63;
        S0[r*LD+c] = S2[r*LD+c] * sl[c];                // W = V*diag^s
    }
    __syncthreads();
    if (noB) {
        mm64<true>(S0, S2, out + (size_t)n * MATSZ, 64);      // Xn = W·Vᵀ
    } else {
        mm64<true>(S0, S2, S1, LD);   __syncthreads();        // P -> S1
        for (int i = tid; i < MATSZ; i += 256) { int r=i>>6,c=i&63; S0[r*LD+c] = g_Bsq[i]; }
        __syncthreads();
        mm64<false>(S0, S1, S2, LD);  __syncthreads();        // Bsq·P -> S2
        mm64<false>(S2, S0, out + (size_t)n * MATSZ, 64);     // Xn
    }
}

// ---------------- launch ----------------
extern "C" void kernel_launch(void* const* d_in, const int* in_sizes, int n_in,
                              void* d_out, int out_size) {
    const float* X    = (const float*)d_in[0];
    const int*   dd   = (const int*)  d_in[1];
    const float* mean = (const float*)d_in[2];
    const float* stdv = (const float*)d_in[3];
    float* out = (float*)d_out;

    const int SM3 = 3 * BUF * (int)sizeof(float);   // 49,920 B -> 4 blocks/SM
    const int SM5 = 5 * BUF * (int)sizeof(float);
    cudaFuncSetAttribute(k2_kernel, cudaFuncAttributeMaxDynamicSharedMemorySize, SM3);
    cudaFuncSetAttribute(k3_kernel, cudaFuncAttributeMaxDynamicSharedMemorySize, SM3);
    cudaFuncSetAttribute(k4_kernel, cudaFuncAttributeMaxDynamicSharedMemorySize, SM5);
    cudaFuncSetAttribute(k5_kernel, cudaFuncAttributeMaxDynamicSharedMemorySize, SM3);

    kzero_kernel<<<128, 256>>>();
    k1_kernel<<<dim3(16, 32), 256>>>(X, dd);
    k2_kernel<<<NDOMS, 256, SM3>>>(dd);
    k3_kernel<<<NMAT, 256, SM3>>>(X, dd);
    k3b_kernel<<<dim3(16, 32), 256>>>(dd);
    k4_kernel<<<NDOMS + 1, 256, SM5>>>(mean, stdv);
    k5_kernel<<<NMAT, 256, SM3>>>(X, dd, out);
}

// round 8
// speedup vs baseline: 5.1994x; 1.5755x over previous
#include <cuda_runtime.h>
#include <math.h>

#define NDIM    64
#define LD      65
#define NMAT    4096
#define NDOMS   8
#define MATSZ   (NDIM*NDIM)
#define BUF     (NDIM*LD)
#define MAXSWEEPS 8
#define EIG_EPS 1e-4f
#define EPS_C   1e-5f

// ---------------- device scratch ----------------
__device__ float g_bmsum [NDOMS*MATSZ];
__device__ float g_bm_sq [NDOMS*MATSZ];
__device__ float g_bm_isq[NDOMS*MATSZ];
__device__ float g_GT    [NDOMS*MATSZ];
__device__ float g_rm_isq[NDOMS*MATSZ];
__device__ float g_Bsq   [MATSZ];
__device__ float g_sumsq [NDOMS];
__device__ float g_cnt   [NDOMS];
__device__ float g_s     [NDOMS];
__device__ int   g_noBsq;
__device__ float g_XT [(size_t)NMAT*MATSZ];
__device__ float g_V3 [(size_t)NMAT*MATSZ];

// ---------------- helpers ----------------
__device__ __forceinline__ float blockReduceSum(float v) {
    __shared__ float red[8];
    const unsigned m = 0xffffffffu;
    #pragma unroll
    for (int o = 16; o; o >>= 1) v += __shfl_down_sync(m, v, o);
    if ((threadIdx.x & 31) == 0) red[threadIdx.x >> 5] = v;
    __syncthreads();
    if (threadIdx.x < 32) {
        float x = (threadIdx.x < 8) ? red[threadIdx.x] : 0.0f;
        #pragma unroll
        for (int o = 4; o; o >>= 1) x += __shfl_down_sync(m, x, o);
        if (threadIdx.x == 0) red[0] = x;
    }
    __syncthreads();
    float r = red[0];
    __syncthreads();
    return r;
}

// vectorized global<->smem copies (global side 16B, smem side scalar due to LD=65)
__device__ __forceinline__ void g2s(const float* __restrict__ g, float* __restrict__ S) {
    const float4* g4 = (const float4*)g;
    for (int i = threadIdx.x; i < MATSZ/4; i += 256) {
        float4 v = g4[i];
        int r = i >> 4, c = (i & 15) << 2;
        float* d = S + r*LD + c;
        d[0]=v.x; d[1]=v.y; d[2]=v.z; d[3]=v.w;
    }
}
__device__ __forceinline__ void s2g(const float* __restrict__ S, float* __restrict__ g) {
    float4* g4 = (float4*)g;
    for (int i = threadIdx.x; i < MATSZ/4; i += 256) {
        int r = i >> 4, c = (i & 15) << 2;
        const float* s = S + r*LD + c;
        g4[i] = make_float4(s[0], s[1], s[2], s[3]);
    }
}

template<bool TRANSB>
__device__ __forceinline__ void mm64(const float* __restrict__ A,
                                     const float* __restrict__ B,
                                     float* __restrict__ C, int ldc) {
    const int tid = threadIdx.x;
    const int r0 = (tid >> 4) << 2;
    const int c0 = (tid & 15) << 2;
    float acc[4][4];
    #pragma unroll
    for (int i = 0; i < 4; i++)
        #pragma unroll
        for (int j = 0; j < 4; j++) acc[i][j] = 0.0f;
    #pragma unroll 4
    for (int k = 0; k < 64; k++) {
        float a0 = A[(r0+0)*LD + k];
        float a1 = A[(r0+1)*LD + k];
        float a2 = A[(r0+2)*LD + k];
        float a3 = A[(r0+3)*LD + k];
        float b0, b1, b2, b3;
        if (TRANSB) {
            b0 = B[(c0+0)*LD + k]; b1 = B[(c0+1)*LD + k];
            b2 = B[(c0+2)*LD + k]; b3 = B[(c0+3)*LD + k];
        } else {
            b0 = B[k*LD + c0+0]; b1 = B[k*LD + c0+1];
            b2 = B[k*LD + c0+2]; b3 = B[k*LD + c0+3];
        }
        acc[0][0] += a0*b0; acc[0][1] += a0*b1; acc[0][2] += a0*b2; acc[0][3] += a0*b3;
        acc[1][0] += a1*b0; acc[1][1] += a1*b1; acc[1][2] += a1*b2; acc[1][3] += a1*b3;
        acc[2][0] += a2*b0; acc[2][1] += a2*b1; acc[2][2] += a2*b2; acc[2][3] += a2*b3;
        acc[3][0] += a3*b0; acc[3][1] += a3*b1; acc[3][2] += a3*b2; acc[3][3] += a3*b3;
    }
    #pragma unroll
    for (int i = 0; i < 4; i++)
        #pragma unroll
        for (int j = 0; j < 4; j++)
            C[(size_t)(r0+i)*ldc + c0 + j] = acc[i][j];
}

// C = A^T * B  (both smem, stride LD)
__device__ __forceinline__ void mm64_tA(const float* __restrict__ A,
                                        const float* __restrict__ B,
                                        float* __restrict__ C) {
    const int tid = threadIdx.x;
    const int r0 = (tid >> 4) << 2;
    const int c0 = (tid & 15) << 2;
    float acc[4][4];
    #pragma unroll
    for (int i = 0; i < 4; i++)
        #pragma unroll
        for (int j = 0; j < 4; j++) acc[i][j] = 0.0f;
    #pragma unroll 4
    for (int k = 0; k < 64; k++) {
        float a0 = A[k*LD + r0+0];
        float a1 = A[k*LD + r0+1];
        float a2 = A[k*LD + r0+2];
        float a3 = A[k*LD + r0+3];
        float b0 = B[k*LD + c0+0], b1 = B[k*LD + c0+1];
        float b2 = B[k*LD + c0+2], b3 = B[k*LD + c0+3];
        acc[0][0] += a0*b0; acc[0][1] += a0*b1; acc[0][2] += a0*b2; acc[0][3] += a0*b3;
        acc[1][0] += a1*b0; acc[1][1] += a1*b1; acc[1][2] += a1*b2; acc[1][3] += a1*b3;
        acc[2][0] += a2*b0; acc[2][1] += a2*b1; acc[2][2] += a2*b2; acc[2][3] += a2*b3;
        acc[3][0] += a3*b0; acc[3][1] += a3*b1; acc[3][2] += a3*b2; acc[3][3] += a3*b3;
    }
    #pragma unroll
    for (int i = 0; i < 4; i++)
        #pragma unroll
        for (int j = 0; j < 4; j++)
            C[(r0+i)*LD + c0 + j] = acc[i][j];
}

__device__ __forceinline__ void symmetrize(const float* __restrict__ S, float* __restrict__ D) {
    for (int i = threadIdx.x; i < MATSZ; i += 256) {
        int r = i >> 6, c = i & 63;
        D[r*LD+c] = 0.5f*(S[r*LD+c] + S[c*LD+r]);
    }
}

// Block-parallel cyclic Jacobi. INITV: set V=I (cold) or use preloaded V (warm start).
// Pre-sweep convergence check lets warm-started blocks exit without paying a sweep.
template<bool INITV>
__device__ void jacobi_eig(float* A, float* V, float tol) {
    const int tid  = threadIdx.x;
    const int warp = tid >> 5;
    const int lane = tid & 31;
    const unsigned FULL = 0xffffffffu;
    if (INITV) {
        for (int i = tid; i < MATSZ; i += 256) {
            int r = i >> 6, c = i & 63;
            V[r*LD+c] = (r == c) ? 1.0f : 0.0f;
        }
        __syncthreads();
    }
    for (int sw = 0; sw < MAXSWEEPS; sw++) {
        // convergence check BEFORE the sweep
        float offs = 0.0f, tots = 0.0f;
        for (int i = tid; i < MATSZ; i += 256) {
            int r = i >> 6, c = i & 63;
            float a = A[r*LD+c], a2 = a*a;
            tots += a2;
            if (r != c) offs += a2;
        }
        float offT = blockReduceSum(offs);
        float totT = blockReduceSum(tots);
        if (offT <= tol * totT + 1e-30f) break;

        for (int rd = 0; rd < 63; rd++) {
            const int x = (rd * 32) % 63;
            int myp = 0, myq = 0; float myc = 1.0f, mys = 0.0f;
            if (lane < 4) {
                const int slot = warp * 4 + lane;
                if (slot == 0) { myp = x; myq = 63; }
                else {
                    int a = x + slot; if (a >= 63) a -= 63;
                    int b = x - slot; if (b < 0)   b += 63;
                    myp = min(a, b); myq = max(a, b);
                }
                const float apq = A[myp*LD+myq];
                const float app = A[myp*LD+myp];
                const float aqq = A[myq*LD+myq];
                if (fabsf(apq) > 2e-7f * (fabsf(app) + fabsf(aqq))) {
                    const float tau = (aqq - app) / (2.0f * apq);
                    float t = 1.0f / (fabsf(tau) + sqrtf(1.0f + tau*tau));
                    if (tau < 0.0f) t = -t;
                    myc = rsqrtf(1.0f + t*t);
                    mys = t * myc;
                }
            }
            int pp[4], qq[4]; float cc[4], ssv[4];
            #pragma unroll
            for (int t = 0; t < 4; t++) {
                pp[t]  = __shfl_sync(FULL, myp, t);
                qq[t]  = __shfl_sync(FULL, myq, t);
                cc[t]  = __shfl_sync(FULL, myc, t);
                ssv[t] = __shfl_sync(FULL, mys, t);
            }
            #pragma unroll
            for (int t = 0; t < 4; t++) {           // ROW phase
                const float c = cc[t], s = ssv[t];
                if (s != 0.0f) {
                    float* Ap = A + pp[t]*LD;
                    float* Aq = A + qq[t]*LD;
                    #pragma unroll
                    for (int kk = 0; kk < 2; kk++) {
                        const int k = lane + 32*kk;
                        const float ap = Ap[k], aq = Aq[k];
                        Ap[k] = c*ap - s*aq;
                        Aq[k] = s*ap + c*aq;
                    }
                }
            }
            __syncthreads();
            float* Ar0 = A + lane*LD;
            float* Vr0 = V + lane*LD;
            #pragma unroll
            for (int t = 0; t < 4; t++) {           // COL phase
                const float c = cc[t], s = ssv[t];
                if (s != 0.0f) {
                    const int p = pp[t], q = qq[t];
                    #pragma unroll
                    for (int kk = 0; kk < 2; kk++) {
                        float* Ar = Ar0 + 32*LD*kk;
                        float* Vr = Vr0 + 32*LD*kk;
                        const float ap = Ar[p], aq = Ar[q];
                        Ar[p] = c*ap - s*aq;
                        Ar[q] = s*ap + c*aq;
                        const float vp = Vr[p], vq = Vr[q];
                        Vr[p] = c*vp - s*vq;
                        Vr[q] = s*vp + c*vq;
                    }
                }
            }
            __syncthreads();
        }
    }
}

// ---------------- kernels ----------------
__global__ void kzero_kernel() {
    int i = blockIdx.x * blockDim.x + threadIdx.x;
    int stride = gridDim.x * blockDim.x;
    for (int j = i; j < NDOMS*MATSZ; j += stride) { g_bmsum[j] = 0.0f; g_GT[j] = 0.0f; }
    if (i < NDOMS) g_sumsq[i] = 0.0f;
}

__global__ void __launch_bounds__(256) k1_kernel(const float* __restrict__ X,
                                                 const int* __restrict__ dd) {
    __shared__ int sdom[128];
    const int e  = blockIdx.x * 256 + threadIdx.x;
    const int n0 = blockIdx.y * 128;
    if (threadIdx.x < 128) sdom[threadIdx.x] = dd[n0 + threadIdx.x];
    __syncthreads();
    float acc[NDOMS];
    #pragma unroll
    for (int k = 0; k < NDOMS; k++) acc[k] = 0.0f;
    for (int m = 0; m < 128; m++) {
        float x = X[(size_t)(n0 + m) * MATSZ + e];
        int dom = sdom[m];
        #pragma unroll
        for (int k = 0; k < NDOMS; k++) acc[k] += (dom == k) ? x : 0.0f;
    }
    #pragma unroll
    for (int k = 0; k < NDOMS; k++) atomicAdd(&g_bmsum[k*MATSZ + e], acc[k]);
}

__global__ void __launch_bounds__(256) k2_kernel(const int* __restrict__ dd) {
    extern __shared__ float sm[];
    float* SX = sm; float* SA = sm + BUF; float* SV = sm + 2*BUF;
    __shared__ float sl[64];
    const int dom = blockIdx.x, tid = threadIdx.x;

    float loc = 0.0f;
    for (int i = tid; i < NMAT; i += 256) loc += (dd[i] == dom) ? 1.0f : 0.0f;
    float cnt  = blockReduceSum(loc);
    float cntf = fmaxf(cnt, 1.0f);
    if (tid == 0) g_cnt[dom] = cntf;

    for (int i = tid; i < MATSZ; i += 256) {
        int r = i >> 6, c = i & 63;
        SX[r*LD+c] = g_bmsum[dom*MATSZ + i] / cntf;
    }
    __syncthreads();
    symmetrize(SX, SA);
    __syncthreads();
    jacobi_eig<true>(SA, SV, 1e-8f);
    if (tid < 64) sl[tid] = fmaxf(SA[tid*LD+tid], EIG_EPS);
    __syncthreads();
    for (int i = tid; i < MATSZ; i += 256) {
        int r = i >> 6, c = i & 63;
        SX[r*LD+c] = SV[r*LD+c] * sqrtf(sl[c]);
    }
    __syncthreads();
    mm64<true>(SX, SV, g_bm_sq + dom*MATSZ, 64);
    __syncthreads();
    for (int i = tid; i < MATSZ; i += 256) {
        int r = i >> 6, c = i & 63;
        SX[r*LD+c] = SV[r*LD+c] / sqrtf(sl[c]);
    }
    __syncthreads();
    mm64<true>(SX, SV, g_bm_isq + dom*MATSZ, 64);
}

// per-element: XT = logm(bm_isq X bm_isq) -> g_XT ; eigenvectors -> g_V3 ; sumsq via eigs.
__global__ void __launch_bounds__(256) k3_kernel(const float* __restrict__ X,
                                                 const int* __restrict__ dd) {
    extern __shared__ float sm[];
    float* S0 = sm; float* S1 = sm + BUF; float* S2 = sm + 2*BUF;
    __shared__ float sl[64];
    const int n = blockIdx.x, tid = threadIdx.x;
    const int dom = dd[n];
    g2s(X + (size_t)n * MATSZ, S0);
    g2s(g_bm_isq + dom * MATSZ, S1);
    __syncthreads();
    mm64<false>(S1, S0, S2, LD);  __syncthreads();   // T = Q·X
    mm64<false>(S2, S1, S0, LD);  __syncthreads();   // M = T·Q
    symmetrize(S0, S1);           __syncthreads();
    jacobi_eig<true>(S1, S2, 1e-7f);                 // A=S1, V=S2
    float lv = 0.0f;
    if (tid < 64) { lv = logf(fmaxf(S1[tid*LD+tid], EIG_EPS)); sl[tid] = lv; }
    float sq = blockReduceSum(lv * lv);
    if (tid == 0) atomicAdd(&g_sumsq[dom], sq);
    s2g(S2, g_V3 + (size_t)n * MATSZ);               // save eigenvectors for k5 warm start
    for (int i = tid; i < MATSZ; i += 256) {
        int r = i >> 6, c = i & 63;
        S0[r*LD+c] = S2[r*LD+c] * sl[c];             // W = V*diag(logλ)
    }
    __syncthreads();
    mm64<true>(S0, S2, g_XT + (size_t)n * MATSZ, 64);  // XT = W·Vᵀ
}

__global__ void __launch_bounds__(256) k3b_kernel(const int* __restrict__ dd) {
    __shared__ int sdom[128];
    const int e  = blockIdx.x * 256 + threadIdx.x;
    const int n0 = blockIdx.y * 128;
    if (threadIdx.x < 128) sdom[threadIdx.x] = dd[n0 + threadIdx.x];
    __syncthreads();
    float acc[NDOMS];
    #pragma unroll
    for (int k = 0; k < NDOMS; k++) acc[k] = 0.0f;
    for (int m = 0; m < 128; m++) {
        float x = g_XT[(size_t)(n0 + m) * MATSZ + e];
        int dom = sdom[m];
        #pragma unroll
        for (int k = 0; k < NDOMS; k++) acc[k] += (dom == k) ? x : 0.0f;
    }
    #pragma unroll
    for (int k = 0; k < NDOMS; k++) atomicAdd(&g_GT[k*MATSZ + e], acc[k]);
}

// per-domain (ETA=1 exact shortcuts): bm1 = bm_sq expm(GT) bm_sq; rm = bm1;
// GT2 = GT  =>  var = sumsq/cnt - ||GT||^2.  Two eigs instead of three.
__global__ void __launch_bounds__(256) k4_kernel(const float* __restrict__ mean,
                                                 const float* __restrict__ stdv) {
    extern __shared__ float sm[];
    float* SA = sm;           float* SV = sm + BUF;
    float* SQ = sm + 2*BUF;   float* SX = sm + 3*BUF;
    float* SG = sm + 4*BUF;
    __shared__ float sl[64];
    const int tid = threadIdx.x, b = blockIdx.x;

    if (b == NDOMS) {   // B_sq = sqrtm(mean) + identity detection
        float dev = 0.0f;
        for (int i = tid; i < MATSZ; i += 256) {
            int r = i >> 6, c = i & 63;
            float mv = mean[i];
            SX[r*LD+c] = mv;
            dev += fabsf(mv - ((r == c) ? 1.0f : 0.0f));
        }
        float devT = blockReduceSum(dev);
        if (tid == 0) g_noBsq = (devT < 1e-6f) ? 1 : 0;
        __syncthreads();
        symmetrize(SX, SA); __syncthreads();
        jacobi_eig<true>(SA, SV, 1e-8f);
        if (tid < 64) sl[tid] = sqrtf(fmaxf(SA[tid*LD+tid], EIG_EPS));
        __syncthreads();
        for (int i = tid; i < MATSZ; i += 256) { int r=i>>6,c=i&63; SX[r*LD+c] = SV[r*LD+c]*sl[c]; }
        __syncthreads();
        mm64<true>(SX, SV, g_Bsq, 64);
        return;
    }
    const int dom = b;
    const float cntf = g_cnt[dom];
    float gn = 0.0f;
    for (int i = tid; i < MATSZ; i += 256) {
        int r = i >> 6, c = i & 63;
        float g = g_GT[dom*MATSZ+i] / cntf;
        SG[r*LD+c] = g;
        gn += g * g;
    }
    float gnorm2 = blockReduceSum(gn);      // ||GT||^2 (pre-symmetrize; GT symmetric anyway)
    __syncthreads();
    symmetrize(SG, SA); __syncthreads();
    jacobi_eig<true>(SA, SV, 1e-8f);        // eig(GT)
    if (tid < 64) sl[tid] = expf(SA[tid*LD+tid]);
    __syncthreads();
    for (int i = tid; i < MATSZ; i += 256) { int r=i>>6,c=i&63; SX[r*LD+c] = SV[r*LD+c]*sl[c]; }
    __syncthreads();
    mm64<true>(SX, SV, SQ, LD); __syncthreads();      // E = expm(GT)
    for (int i = tid; i < MATSZ; i += 256) { int r=i>>6,c=i&63; SA[r*LD+c] = g_bm_sq[dom*MATSZ+i]; }
    __syncthreads();
    mm64<false>(SA, SQ, SX, LD); __syncthreads();     // bm_sq·E
    mm64<false>(SX, SA, SV, LD); __syncthreads();     // bm1 = rm
    symmetrize(SV, SA); __syncthreads();
    jacobi_eig<true>(SA, SQ, 1e-8f);                  // eig(rm), U in SQ
    if (tid < 64) sl[tid] = fmaxf(SA[tid*LD+tid], EIG_EPS);
    __syncthreads();
    for (int i = tid; i < MATSZ; i += 256) { int r=i>>6,c=i&63; SX[r*LD+c] = SQ[r*LD+c]*rsqrtf(sl[c]); }
    __syncthreads();
    mm64<true>(SX, SQ, g_rm_isq + dom*MATSZ, 64);     // rm_isq
    if (tid == 0) {
        float var = g_sumsq[dom] / cntf - gnorm2;     // GT2 == GT (ETA=1, exact)
        g_s[dom]  = stdv[0] / sqrtf(var + EPS_C);     // rv = var (ETA=1)
    }
}

// per-element normalize, warm-started from k3's eigenvectors.
__global__ void __launch_bounds__(256) k5_kernel(const float* __restrict__ X,
                                                 const int* __restrict__ dd,
                                                 float* __restrict__ out) {
    extern __shared__ float sm[];
    float* S0 = sm; float* S1 = sm + BUF; float* S2 = sm + 2*BUF;
    __shared__ float sl[64];
    const int n = blockIdx.x, tid = threadIdx.x;
    const int dom = dd[n];
    const int noB = g_noBsq;
    g2s(X + (size_t)n * MATSZ, S0);
    g2s(g_rm_isq + dom * MATSZ, S1);
    __syncthreads();
    mm64<false>(S1, S0, S2, LD);  __syncthreads();   // T = Q5·X
    mm64<false>(S2, S1, S0, LD);  __syncthreads();   // M5 = T·Q5   (S1 dead)
    g2s(g_V3 + (size_t)n * MATSZ, S1);               // V3
    __syncthreads();
    mm64<false>(S0, S1, S2, LD);  __syncthreads();   // W = M5·V3   (S0 dead after next)
    mm64_tA(S1, S2, S0);          __syncthreads();   // A' = V3ᵀ·W
    symmetrize(S0, S2);           __syncthreads();   // A = sym(A') -> S2
    jacobi_eig<false>(S2, S1, 1e-8f);                // V preloaded with V3; full V accumulates in S1
    const float sgl = g_s[dom];
    if (tid < 64) sl[tid] = expf(sgl * logf(fmaxf(S2[tid*LD+tid], EIG_EPS)));
    __syncthreads();
    for (int i = tid; i < MATSZ; i += 256) {
        int r = i >> 6, c = i & 63;
        S0[r*LD+c] = S1[r*LD+c] * sl[c];             // W = V·diag(λ^s)
    }
    __syncthreads();
    if (noB) {
        mm64<true>(S0, S1, out + (size_t)n * MATSZ, 64);   // Xn = W·Vᵀ
    } else {
        mm64<true>(S0, S1, S2, LD);   __syncthreads();     // P
        for (int i = tid; i < MATSZ; i += 256) { int r=i>>6,c=i&63; S0[r*LD+c] = g_Bsq[i]; }
        __syncthreads();
        mm64<false>(S0, S2, S1, LD);  __syncthreads();     // Bsq·P
        mm64<false>(S1, S0, out + (size_t)n * MATSZ, 64);  // Xn
    }
}

// ---------------- launch ----------------
extern "C" void kernel_launch(void* const* d_in, const int* in_sizes, int n_in,
                              void* d_out, int out_size) {
    const float* X    = (const float*)d_in[0];
    const int*   dd   = (const int*)  d_in[1];
    const float* mean = (const float*)d_in[2];
    const float* stdv = (const float*)d_in[3];
    float* out = (float*)d_out;

    const int SM3 = 3 * BUF * (int)sizeof(float);   // 49,920 B -> 4 blocks/SM
    const int SM5 = 5 * BUF * (int)sizeof(float);
    cudaFuncSetAttribute(k2_kernel, cudaFuncAttributeMaxDynamicSharedMemorySize, SM3);
    cudaFuncSetAttribute(k3_kernel, cudaFuncAttributeMaxDynamicSharedMemorySize, SM3);
    cudaFuncSetAttribute(k4_kernel, cudaFuncAttributeMaxDynamicSharedMemorySize, SM5);
    cudaFuncSetAttribute(k5_kernel, cudaFuncAttributeMaxDynamicSharedMemorySize, SM3);

    kzero_kernel<<<128, 256>>>();
    k1_kernel<<<dim3(16, 32), 256>>>(X, dd);
    k2_kernel<<<NDOMS, 256, SM3>>>(dd);
    k3_kernel<<<NMAT, 256, SM3>>>(X, dd);
    k3b_kernel<<<dim3(16, 32), 256>>>(dd);
    k4_kernel<<<NDOMS + 1, 256, SM5>>>(mean, stdv);
    k5_kernel<<<NMAT, 256, SM3>>>(X, dd, out);
}

// round 9
// speedup vs baseline: 6.3718x; 1.2255x over previous
#include <cuda_runtime.h>
#include <math.h>

#define NDIM    64
#define LD      65
#define NMAT    4096
#define NDOMS   8
#define MATSZ   (NDIM*NDIM)
#define BUF     (NDIM*LD)
#define MAXSWEEPS 8
#define EIG_EPS 1e-4f
#define EPS_C   1e-5f

// ---------------- device scratch ----------------
__device__ float g_bmsum [NDOMS*MATSZ];
__device__ float g_bm_sq [NDOMS*MATSZ];
__device__ float g_bm_isq[NDOMS*MATSZ];
__device__ float g_GT    [NDOMS*MATSZ];
__device__ float g_rm_isq[NDOMS*MATSZ];
__device__ float g_Bsq   [MATSZ];
__device__ float g_sumsq [NDOMS];
__device__ float g_cnt   [NDOMS];
__device__ float g_s     [NDOMS];
__device__ int   g_noBsq;
__device__ float g_XT [(size_t)NMAT*MATSZ];
__device__ float g_V3 [(size_t)NMAT*MATSZ];

// ---------------- helpers ----------------
__device__ __forceinline__ float blockReduceSum(float v) {
    __shared__ float red[8];
    const unsigned m = 0xffffffffu;
    #pragma unroll
    for (int o = 16; o; o >>= 1) v += __shfl_down_sync(m, v, o);
    if ((threadIdx.x & 31) == 0) red[threadIdx.x >> 5] = v;
    __syncthreads();
    if (threadIdx.x < 32) {
        float x = (threadIdx.x < 8) ? red[threadIdx.x] : 0.0f;
        #pragma unroll
        for (int o = 4; o; o >>= 1) x += __shfl_down_sync(m, x, o);
        if (threadIdx.x == 0) red[0] = x;
    }
    __syncthreads();
    float r = red[0];
    __syncthreads();
    return r;
}

__device__ __forceinline__ void g2s(const float* __restrict__ g, float* __restrict__ S) {
    const float4* g4 = (const float4*)g;
    for (int i = threadIdx.x; i < MATSZ/4; i += 256) {
        float4 v = g4[i];
        int r = i >> 4, c = (i & 15) << 2;
        float* d = S + r*LD + c;
        d[0]=v.x; d[1]=v.y; d[2]=v.z; d[3]=v.w;
    }
}
__device__ __forceinline__ void s2g(const float* __restrict__ S, float* __restrict__ g) {
    float4* g4 = (float4*)g;
    for (int i = threadIdx.x; i < MATSZ/4; i += 256) {
        int r = i >> 4, c = (i & 15) << 2;
        const float* s = S + r*LD + c;
        g4[i] = make_float4(s[0], s[1], s[2], s[3]);
    }
}

template<bool TRANSB>
__device__ __forceinline__ void mm64(const float* __restrict__ A,
                                     const float* __restrict__ B,
                                     float* __restrict__ C, int ldc) {
    const int tid = threadIdx.x;
    const int r0 = (tid >> 4) << 2;
    const int c0 = (tid & 15) << 2;
    float acc[4][4];
    #pragma unroll
    for (int i = 0; i < 4; i++)
        #pragma unroll
        for (int j = 0; j < 4; j++) acc[i][j] = 0.0f;
    #pragma unroll 4
    for (int k = 0; k < 64; k++) {
        float a0 = A[(r0+0)*LD + k];
        float a1 = A[(r0+1)*LD + k];
        float a2 = A[(r0+2)*LD + k];
        float a3 = A[(r0+3)*LD + k];
        float b0, b1, b2, b3;
        if (TRANSB) {
            b0 = B[(c0+0)*LD + k]; b1 = B[(c0+1)*LD + k];
            b2 = B[(c0+2)*LD + k]; b3 = B[(c0+3)*LD + k];
        } else {
            b0 = B[k*LD + c0+0]; b1 = B[k*LD + c0+1];
            b2 = B[k*LD + c0+2]; b3 = B[k*LD + c0+3];
        }
        acc[0][0] += a0*b0; acc[0][1] += a0*b1; acc[0][2] += a0*b2; acc[0][3] += a0*b3;
        acc[1][0] += a1*b0; acc[1][1] += a1*b1; acc[1][2] += a1*b2; acc[1][3] += a1*b3;
        acc[2][0] += a2*b0; acc[2][1] += a2*b1; acc[2][2] += a2*b2; acc[2][3] += a2*b3;
        acc[3][0] += a3*b0; acc[3][1] += a3*b1; acc[3][2] += a3*b2; acc[3][3] += a3*b3;
    }
    #pragma unroll
    for (int i = 0; i < 4; i++)
        #pragma unroll
        for (int j = 0; j < 4; j++)
            C[(size_t)(r0+i)*ldc + c0 + j] = acc[i][j];
}

// C = A^T * B (both smem, stride LD)
__device__ __forceinline__ void mm64_tA(const float* __restrict__ A,
                                        const float* __restrict__ B,
                                        float* __restrict__ C) {
    const int tid = threadIdx.x;
    const int r0 = (tid >> 4) << 2;
    const int c0 = (tid & 15) << 2;
    float acc[4][4];
    #pragma unroll
    for (int i = 0; i < 4; i++)
        #pragma unroll
        for (int j = 0; j < 4; j++) acc[i][j] = 0.0f;
    #pragma unroll 4
    for (int k = 0; k < 64; k++) {
        float a0 = A[k*LD + r0+0];
        float a1 = A[k*LD + r0+1];
        float a2 = A[k*LD + r0+2];
        float a3 = A[k*LD + r0+3];
        float b0 = B[k*LD + c0+0], b1 = B[k*LD + c0+1];
        float b2 = B[k*LD + c0+2], b3 = B[k*LD + c0+3];
        acc[0][0] += a0*b0; acc[0][1] += a0*b1; acc[0][2] += a0*b2; acc[0][3] += a0*b3;
        acc[1][0] += a1*b0; acc[1][1] += a1*b1; acc[1][2] += a1*b2; acc[1][3] += a1*b3;
        acc[2][0] += a2*b0; acc[2][1] += a2*b1; acc[2][2] += a2*b2; acc[2][3] += a2*b3;
        acc[3][0] += a3*b0; acc[3][1] += a3*b1; acc[3][2] += a3*b2; acc[3][3] += a3*b3;
    }
    #pragma unroll
    for (int i = 0; i < 4; i++)
        #pragma unroll
        for (int j = 0; j < 4; j++)
            C[(r0+i)*LD + c0 + j] = acc[i][j];
}

__device__ __forceinline__ void symmetrize(const float* __restrict__ S, float* __restrict__ D) {
    for (int i = threadIdx.x; i < MATSZ; i += 256) {
        int r = i >> 6, c = i & 63;
        D[r*LD+c] = 0.5f*(S[r*LD+c] + S[c*LD+r]);
    }
}

// ---- two-sided Jacobi (kept for the tiny per-domain kernels; handles indefinite) ----
template<bool INITV>
__device__ void jacobi_eig(float* A, float* V, float tol) {
    const int tid  = threadIdx.x;
    const int warp = tid >> 5;
    const int lane = tid & 31;
    const unsigned FULL = 0xffffffffu;
    if (INITV) {
        for (int i = tid; i < MATSZ; i += 256) {
            int r = i >> 6, c = i & 63;
            V[r*LD+c] = (r == c) ? 1.0f : 0.0f;
        }
        __syncthreads();
    }
    for (int sw = 0; sw < MAXSWEEPS; sw++) {
        float offs = 0.0f, tots = 0.0f;
        for (int i = tid; i < MATSZ; i += 256) {
            int r = i >> 6, c = i & 63;
            float a = A[r*LD+c], a2 = a*a;
            tots += a2;
            if (r != c) offs += a2;
        }
        float offT = blockReduceSum(offs);
        float totT = blockReduceSum(tots);
        if (offT <= tol * totT + 1e-30f) break;

        for (int rd = 0; rd < 63; rd++) {
            const int x = (rd * 32) % 63;
            int myp = 0, myq = 0; float myc = 1.0f, mys = 0.0f;
            if (lane < 4) {
                const int slot = warp * 4 + lane;
                if (slot == 0) { myp = x; myq = 63; }
                else {
                    int a = x + slot; if (a >= 63) a -= 63;
                    int b = x - slot; if (b < 0)   b += 63;
                    myp = min(a, b); myq = max(a, b);
                }
                const float apq = A[myp*LD+myq];
                const float app = A[myp*LD+myp];
                const float aqq = A[myq*LD+myq];
                if (fabsf(apq) > 2e-7f * (fabsf(app) + fabsf(aqq))) {
                    const float tau = (aqq - app) / (2.0f * apq);
                    float t = 1.0f / (fabsf(tau) + sqrtf(1.0f + tau*tau));
                    if (tau < 0.0f) t = -t;
                    myc = rsqrtf(1.0f + t*t);
                    mys = t * myc;
                }
            }
            int pp[4], qq[4]; float cc[4], ssv[4];
            #pragma unroll
            for (int t = 0; t < 4; t++) {
                pp[t]  = __shfl_sync(FULL, myp, t);
                qq[t]  = __shfl_sync(FULL, myq, t);
                cc[t]  = __shfl_sync(FULL, myc, t);
                ssv[t] = __shfl_sync(FULL, mys, t);
            }
            #pragma unroll
            for (int t = 0; t < 4; t++) {
                const float c = cc[t], s = ssv[t];
                if (s != 0.0f) {
                    float* Ap = A + pp[t]*LD;
                    float* Aq = A + qq[t]*LD;
                    #pragma unroll
                    for (int kk = 0; kk < 2; kk++) {
                        const int k = lane + 32*kk;
                        const float ap = Ap[k], aq = Aq[k];
                        Ap[k] = c*ap - s*aq;
                        Aq[k] = s*ap + c*aq;
                    }
                }
            }
            __syncthreads();
            float* Ar0 = A + lane*LD;
            float* Vr0 = V + lane*LD;
            #pragma unroll
            for (int t = 0; t < 4; t++) {
                const float c = cc[t], s = ssv[t];
                if (s != 0.0f) {
                    const int p = pp[t], q = qq[t];
                    #pragma unroll
                    for (int kk = 0; kk < 2; kk++) {
                        float* Ar = Ar0 + 32*LD*kk;
                        float* Vr = Vr0 + 32*LD*kk;
                        const float ap = Ar[p], aq = Ar[q];
                        Ar[p] = c*ap - s*aq;
                        Ar[q] = s*ap + c*aq;
                        const float vp = Vr[p], vq = Vr[q];
                        Vr[p] = c*vp - s*vq;
                        Vr[q] = s*vp + c*vq;
                    }
                }
            }
            __syncthreads();
        }
    }
}

// ---- one-sided Jacobi for SPD matrices (the hot path) ----
// B (smem, stride LD) is rotated in place: B <- B*J...  On exit, columns of B are
// orthogonal; lambda_j = ||B[:,j]||, v_j = B[:,j]/lambda_j  (valid since B0 is SPD).
// 8 warps x 4 groups of 8 lanes; warp w owns slots {w, w+8, w+16, w+24} so the four
// column-bank windows tile all 32 banks. One barrier per round.
__device__ void jacobi_onesided(float* B, int* s_changed) {
    const int tid  = threadIdx.x;
    const int warp = tid >> 5;
    const int grp  = (tid & 31) >> 3;
    const int gl   = tid & 7;
    const unsigned FULL = 0xffffffffu;
    const int slot = warp + 8*grp;
    if (tid == 0) *s_changed = 0;
    __syncthreads();
    for (int sw = 0; sw < MAXSWEEPS; sw++) {
        for (int rd = 0; rd < 63; rd++) {
            const int x = (rd * 32) % 63;
            int p, q;
            if (slot == 0) { p = x; q = 63; }
            else {
                int a = x + slot; if (a >= 63) a -= 63;
                int b = x - slot; if (b < 0)   b += 63;
                p = min(a, b); q = max(a, b);
            }
            float bp[8], bq[8];
            float dpp = 0.0f, dqq = 0.0f, dpq = 0.0f;
            #pragma unroll
            for (int i = 0; i < 8; i++) {
                const int k = gl + 8*i;
                bp[i] = B[k*LD + p];
                bq[i] = B[k*LD + q];
                dpp += bp[i]*bp[i];
                dqq += bq[i]*bq[i];
                dpq += bp[i]*bq[i];
            }
            #pragma unroll
            for (int o = 4; o; o >>= 1) {
                dpp += __shfl_xor_sync(FULL, dpp, o, 8);
                dqq += __shfl_xor_sync(FULL, dqq, o, 8);
                dpq += __shfl_xor_sync(FULL, dpq, o, 8);
            }
            if (dpq*dpq > 4e-14f * dpp * dqq) {
                const float tau = (dqq - dpp) / (2.0f * dpq);
                float t = 1.0f / (fabsf(tau) + sqrtf(1.0f + tau*tau));
                if (tau < 0.0f) t = -t;
                const float c = rsqrtf(1.0f + t*t);
                const float s = t * c;
                #pragma unroll
                for (int i = 0; i < 8; i++) {
                    const int k = gl + 8*i;
                    B[k*LD + p] = c*bp[i] - s*bq[i];
                    B[k*LD + q] = s*bp[i] + c*bq[i];
                }
                if (gl == 0) *s_changed = 1;
            }
            __syncthreads();
        }
        const int ch = *s_changed;
        __syncthreads();
        if (ch == 0) break;
        if (tid == 0) *s_changed = 0;
        __syncthreads();
    }
}

// ---------------- kernels ----------------
__global__ void kzero_kernel() {
    int i = blockIdx.x * blockDim.x + threadIdx.x;
    int stride = gridDim.x * blockDim.x;
    for (int j = i; j < NDOMS*MATSZ; j += stride) { g_bmsum[j] = 0.0f; g_GT[j] = 0.0f; }
    if (i < NDOMS) g_sumsq[i] = 0.0f;
}

__global__ void __launch_bounds__(256) k1_kernel(const float* __restrict__ X,
                                                 const int* __restrict__ dd) {
    __shared__ int sdom[128];
    const int e  = blockIdx.x * 256 + threadIdx.x;
    const int n0 = blockIdx.y * 128;
    if (threadIdx.x < 128) sdom[threadIdx.x] = dd[n0 + threadIdx.x];
    __syncthreads();
    float acc[NDOMS];
    #pragma unroll
    for (int k = 0; k < NDOMS; k++) acc[k] = 0.0f;
    for (int m = 0; m < 128; m++) {
        float x = X[(size_t)(n0 + m) * MATSZ + e];
        int dom = sdom[m];
        #pragma unroll
        for (int k = 0; k < NDOMS; k++) acc[k] += (dom == k) ? x : 0.0f;
    }
    #pragma unroll
    for (int k = 0; k < NDOMS; k++) atomicAdd(&g_bmsum[k*MATSZ + e], acc[k]);
}

__global__ void __launch_bounds__(256) k2_kernel(const int* __restrict__ dd) {
    extern __shared__ float sm[];
    float* SX = sm; float* SA = sm + BUF; float* SV = sm + 2*BUF;
    __shared__ float sl[64];
    const int dom = blockIdx.x, tid = threadIdx.x;

    float loc = 0.0f;
    for (int i = tid; i < NMAT; i += 256) loc += (dd[i] == dom) ? 1.0f : 0.0f;
    float cnt  = blockReduceSum(loc);
    float cntf = fmaxf(cnt, 1.0f);
    if (tid == 0) g_cnt[dom] = cntf;

    for (int i = tid; i < MATSZ; i += 256) {
        int r = i >> 6, c = i & 63;
        SX[r*LD+c] = g_bmsum[dom*MATSZ + i] / cntf;
    }
    __syncthreads();
    symmetrize(SX, SA);
    __syncthreads();
    jacobi_eig<true>(SA, SV, 1e-8f);
    if (tid < 64) sl[tid] = fmaxf(SA[tid*LD+tid], EIG_EPS);
    __syncthreads();
    for (int i = tid; i < MATSZ; i += 256) {
        int r = i >> 6, c = i & 63;
        SX[r*LD+c] = SV[r*LD+c] * sqrtf(sl[c]);
    }
    __syncthreads();
    mm64<true>(SX, SV, g_bm_sq + dom*MATSZ, 64);
    __syncthreads();
    for (int i = tid; i < MATSZ; i += 256) {
        int r = i >> 6, c = i & 63;
        SX[r*LD+c] = SV[r*LD+c] / sqrtf(sl[c]);
    }
    __syncthreads();
    mm64<true>(SX, SV, g_bm_isq + dom*MATSZ, 64);
}

// per-element: one-sided eig of M3 = bm_isq X bm_isq; XT -> g_XT, V3 -> g_V3.
__global__ void __launch_bounds__(256) k3_kernel(const float* __restrict__ X,
                                                 const int* __restrict__ dd) {
    extern __shared__ float sm[];
    float* S0 = sm; float* S1 = sm + BUF; float* S2 = sm + 2*BUF;
    __shared__ float lam[64], slog[64];
    __shared__ int s_flag;
    const int n = blockIdx.x, tid = threadIdx.x;
    const int dom = dd[n];
    g2s(X + (size_t)n * MATSZ, S0);
    g2s(g_bm_isq + dom * MATSZ, S1);
    __syncthreads();
    mm64<false>(S1, S0, S2, LD);  __syncthreads();   // T = Q·X
    mm64<false>(S2, S1, S0, LD);  __syncthreads();   // M = T·Q  -> S0 (B)
    jacobi_onesided(S0, &s_flag);
    if (tid < 64) {                                  // lambda_j = ||B[:,j]||
        float s = 0.0f;
        for (int k = 0; k < 64; k++) { float b = S0[k*LD + tid]; s += b*b; }
        float l = sqrtf(s);
        lam[tid]  = fmaxf(l, 1e-20f);
        slog[tid] = logf(fmaxf(l, EIG_EPS));
    }
    __syncthreads();
    float lv = (tid < 64) ? slog[tid] : 0.0f;
    float sq = blockReduceSum(lv * lv);              // ||logm||_F^2
    if (tid == 0) atomicAdd(&g_sumsq[dom], sq);
    for (int i = tid; i < MATSZ; i += 256) {
        int r = i >> 6, c = i & 63;
        float b = S0[r*LD+c];
        float inv = 1.0f / lam[c];
        S1[r*LD+c] = b * inv;                        // V3
        S2[r*LD+c] = b * (slog[c] * inv);            // W = V3*diag(loglam)
    }
    __syncthreads();
    s2g(S1, g_V3 + (size_t)n * MATSZ);
    mm64<true>(S2, S1, g_XT + (size_t)n * MATSZ, 64);  // XT = W·V3^T
}

__global__ void __launch_bounds__(256) k3b_kernel(const int* __restrict__ dd) {
    __shared__ int sdom[128];
    const int e  = blockIdx.x * 256 + threadIdx.x;
    const int n0 = blockIdx.y * 128;
    if (threadIdx.x < 128) sdom[threadIdx.x] = dd[n0 + threadIdx.x];
    __syncthreads();
    float acc[NDOMS];
    #pragma unroll
    for (int k = 0; k < NDOMS; k++) acc[k] = 0.0f;
    for (int m = 0; m < 128; m++) {
        float x = g_XT[(size_t)(n0 + m) * MATSZ + e];
        int dom = sdom[m];
        #pragma unroll
        for (int k = 0; k < NDOMS; k++) acc[k] += (dom == k) ? x : 0.0f;
    }
    #pragma unroll
    for (int k = 0; k < NDOMS; k++) atomicAdd(&g_GT[k*MATSZ + e], acc[k]);
}

// per-domain (ETA=1 exact): rm = bm1 = bm_sq expm(GT) bm_sq; GT2 = GT; var = sumsq/cnt - ||GT||^2.
__global__ void __launch_bounds__(256) k4_kernel(const float* __restrict__ mean,
                                                 const float* __restrict__ stdv) {
    extern __shared__ float sm[];
    float* SA = sm;           float* SV = sm + BUF;
    float* SQ = sm + 2*BUF;   float* SX = sm + 3*BUF;
    float* SG = sm + 4*BUF;
    __shared__ float sl[64];
    const int tid = threadIdx.x, b = blockIdx.x;

    if (b == NDOMS) {
        float dev = 0.0f;
        for (int i = tid; i < MATSZ; i += 256) {
            int r = i >> 6, c = i & 63;
            float mv = mean[i];
            SX[r*LD+c] = mv;
            dev += fabsf(mv - ((r == c) ? 1.0f : 0.0f));
        }
        float devT = blockReduceSum(dev);
        if (tid == 0) g_noBsq = (devT < 1e-6f) ? 1 : 0;
        __syncthreads();
        symmetrize(SX, SA); __syncthreads();
        jacobi_eig<true>(SA, SV, 1e-8f);
        if (tid < 64) sl[tid] = sqrtf(fmaxf(SA[tid*LD+tid], EIG_EPS));
        __syncthreads();
        for (int i = tid; i < MATSZ; i += 256) { int r=i>>6,c=i&63; SX[r*LD+c] = SV[r*LD+c]*sl[c]; }
        __syncthreads();
        mm64<true>(SX, SV, g_Bsq, 64);
        return;
    }
    const int dom = b;
    const float cntf = g_cnt[dom];
    float gn = 0.0f;
    for (int i = tid; i < MATSZ; i += 256) {
        int r = i >> 6, c = i & 63;
        float g = g_GT[dom*MATSZ+i] / cntf;
        SG[r*LD+c] = g;
        gn += g * g;
    }
    float gnorm2 = blockReduceSum(gn);
    __syncthreads();
    symmetrize(SG, SA); __syncthreads();
    jacobi_eig<true>(SA, SV, 1e-8f);        // eig(GT), indefinite
    if (tid < 64) sl[tid] = expf(SA[tid*LD+tid]);
    __syncthreads();
    for (int i = tid; i < MATSZ; i += 256) { int r=i>>6,c=i&63; SX[r*LD+c] = SV[r*LD+c]*sl[c]; }
    __syncthreads();
    mm64<true>(SX, SV, SQ, LD); __syncthreads();      // E = expm(GT)
    for (int i = tid; i < MATSZ; i += 256) { int r=i>>6,c=i&63; SA[r*LD+c] = g_bm_sq[dom*MATSZ+i]; }
    __syncthreads();
    mm64<false>(SA, SQ, SX, LD); __syncthreads();     // bm_sq·E
    mm64<false>(SX, SA, SV, LD); __syncthreads();     // rm
    symmetrize(SV, SA); __syncthreads();
    jacobi_eig<true>(SA, SQ, 1e-8f);                  // eig(rm)
    if (tid < 64) sl[tid] = fmaxf(SA[tid*LD+tid], EIG_EPS);
    __syncthreads();
    for (int i = tid; i < MATSZ; i += 256) { int r=i>>6,c=i&63; SX[r*LD+c] = SQ[r*LD+c]*rsqrtf(sl[c]); }
    __syncthreads();
    mm64<true>(SX, SQ, g_rm_isq + dom*MATSZ, 64);
    if (tid == 0) {
        float var = g_sumsq[dom] / cntf - gnorm2;
        g_s[dom]  = stdv[0] / sqrtf(var + EPS_C);
    }
}

// per-element normalize, warm-started: A' = V3^T M5 V3 (near-diagonal, SPD) -> one-sided.
__global__ void __launch_bounds__(256) k5_kernel(const float* __restrict__ X,
                                                 const int* __restrict__ dd,
                                                 float* __restrict__ out) {
    extern __shared__ float sm[];
    float* S0 = sm; float* S1 = sm + BUF; float* S2 = sm + 2*BUF;
    __shared__ float lam[64], ff[64];
    __shared__ int s_flag;
    const int n = blockIdx.x, tid = threadIdx.x;
    const int dom = dd[n];
    const int noB = g_noBsq;
    g2s(X + (size_t)n * MATSZ, S0);
    g2s(g_rm_isq + dom * MATSZ, S1);
    __syncthreads();
    mm64<false>(S1, S0, S2, LD);  __syncthreads();   // T = Q5·X
    mm64<false>(S2, S1, S0, LD);  __syncthreads();   // M5 -> S0
    g2s(g_V3 + (size_t)n * MATSZ, S1);               // V3 -> S1
    __syncthreads();
    mm64<false>(S0, S1, S2, LD);  __syncthreads();   // W = M5·V3 -> S2
    mm64_tA(S1, S2, S0);          __syncthreads();   // A' = V3^T·W -> S0 (B)
    jacobi_onesided(S0, &s_flag);
    const float sgl = g_s[dom];
    if (tid < 64) {
        float s = 0.0f;
        for (int k = 0; k < 64; k++) { float b = S0[k*LD + tid]; s += b*b; }
        float l = sqrtf(s);
        lam[tid] = fmaxf(l, 1e-20f);
        ff[tid]  = expf(sgl * logf(fmaxf(l, EIG_EPS)));   // lambda^s
    }
    __syncthreads();
    for (int i = tid; i < MATSZ; i += 256) {
        int r = i >> 6, c = i & 63;
        S2[r*LD+c] = S0[r*LD+c] / lam[c];            // V' (A'-basis eigvecs)
    }
    __syncthreads();
    mm64<false>(S1, S2, S0, LD);  __syncthreads();   // G = V3·V' -> S0 (full eigvecs)
    for (int i = tid; i < MATSZ; i += 256) {
        int r = i >> 6, c = i & 63;
        S2[r*LD+c] = S0[r*LD+c] * ff[c];             // W2 = G·diag(lambda^s)
    }
    __syncthreads();
    if (noB) {
        mm64<true>(S2, S0, out + (size_t)n * MATSZ, 64);    // Xn = W2·G^T
    } else {
        mm64<true>(S2, S0, S1, LD);   __syncthreads();      // P -> S1
        g2s(g_Bsq, S0);               __syncthreads();
        mm64<false>(S0, S1, S2, LD);  __syncthreads();      // Bsq·P
        mm64<false>(S2, S0, out + (size_t)n * MATSZ, 64);   // Xn
    }
}

// ---------------- launch ----------------
extern "C" void kernel_launch(void* const* d_in, const int* in_sizes, int n_in,
                              void* d_out, int out_size) {
    const float* X    = (const float*)d_in[0];
    const int*   dd   = (const int*)  d_in[1];
    const float* mean = (const float*)d_in[2];
    const float* stdv = (const float*)d_in[3];
    float* out = (float*)d_out;

    const int SM3 = 3 * BUF * (int)sizeof(float);   // 49,920 B -> 4 blocks/SM
    const int SM5 = 5 * BUF * (int)sizeof(float);
    cudaFuncSetAttribute(k2_kernel, cudaFuncAttributeMaxDynamicSharedMemorySize, SM3);
    cudaFuncSetAttribute(k3_kernel, cudaFuncAttributeMaxDynamicSharedMemorySize, SM3);
    cudaFuncSetAttribute(k4_kernel, cudaFuncAttributeMaxDynamicSharedMemorySize, SM5);
    cudaFuncSetAttribute(k5_kernel, cudaFuncAttributeMaxDynamicSharedMemorySize, SM3);

    kzero_kernel<<<128, 256>>>();
    k1_kernel<<<dim3(16, 32), 256>>>(X, dd);
    k2_kernel<<<NDOMS, 256, SM3>>>(dd);
    k3_kernel<<<NMAT, 256, SM3>>>(X, dd);
    k3b_kernel<<<dim3(16, 32), 256>>>(dd);
    k4_kernel<<<NDOMS + 1, 256, SM5>>>(mean, stdv);
    k5_kernel<<<NMAT, 256, SM3>>>(X, dd, out);
}

// round 10
// speedup vs baseline: 7.5110x; 1.1788x over previous
#include <cuda_runtime.h>
#include <math.h>

#define NDIM    64
#define LD      65
#define NMAT    4096
#define NDOMS   8
#define MATSZ   (NDIM*NDIM)
#define BUF     (NDIM*LD)
#define MAXSWEEPS 8
#define EIG_EPS 1e-4f
#define EPS_C   1e-5f

// ---------------- device scratch ----------------
__device__ float g_bmsum [NDOMS*MATSZ];
__device__ float g_bm_sq [NDOMS*MATSZ];
__device__ float g_bm_isq[NDOMS*MATSZ];
__device__ float g_GT    [NDOMS*MATSZ];
__device__ float g_rm_isq[NDOMS*MATSZ];
__device__ float g_Bsq   [MATSZ];
__device__ float g_sumsq [NDOMS];
__device__ float g_cnt   [NDOMS];
__device__ float g_s     [NDOMS];
__device__ int   g_noBsq;
__device__ float g_XT [(size_t)NMAT*MATSZ];
__device__ float g_V3 [(size_t)NMAT*MATSZ];

// ---------------- helpers ----------------
__device__ __forceinline__ float blockReduceSum(float v) {
    __shared__ float red[8];
    const unsigned m = 0xffffffffu;
    #pragma unroll
    for (int o = 16; o; o >>= 1) v += __shfl_down_sync(m, v, o);
    if ((threadIdx.x & 31) == 0) red[threadIdx.x >> 5] = v;
    __syncthreads();
    if (threadIdx.x < 32) {
        float x = (threadIdx.x < 8) ? red[threadIdx.x] : 0.0f;
        #pragma unroll
        for (int o = 4; o; o >>= 1) x += __shfl_down_sync(m, x, o);
        if (threadIdx.x == 0) red[0] = x;
    }
    __syncthreads();
    float r = red[0];
    __syncthreads();
    return r;
}

__device__ __forceinline__ void g2s(const float* __restrict__ g, float* __restrict__ S) {
    const float4* g4 = (const float4*)g;
    for (int i = threadIdx.x; i < MATSZ/4; i += 256) {
        float4 v = g4[i];
        int r = i >> 4, c = (i & 15) << 2;
        float* d = S + r*LD + c;
        d[0]=v.x; d[1]=v.y; d[2]=v.z; d[3]=v.w;
    }
}
__device__ __forceinline__ void s2g(const float* __restrict__ S, float* __restrict__ g) {
    float4* g4 = (float4*)g;
    for (int i = threadIdx.x; i < MATSZ/4; i += 256) {
        int r = i >> 4, c = (i & 15) << 2;
        const float* s = S + r*LD + c;
        g4[i] = make_float4(s[0], s[1], s[2], s[3]);
    }
}

template<bool TRANSB>
__device__ __forceinline__ void mm64(const float* __restrict__ A,
                                     const float* __restrict__ B,
                                     float* __restrict__ C, int ldc) {
    const int tid = threadIdx.x;
    const int r0 = (tid >> 4) << 2;
    const int c0 = (tid & 15) << 2;
    float acc[4][4];
    #pragma unroll
    for (int i = 0; i < 4; i++)
        #pragma unroll
        for (int j = 0; j < 4; j++) acc[i][j] = 0.0f;
    #pragma unroll 4
    for (int k = 0; k < 64; k++) {
        float a0 = A[(r0+0)*LD + k];
        float a1 = A[(r0+1)*LD + k];
        float a2 = A[(r0+2)*LD + k];
        float a3 = A[(r0+3)*LD + k];
        float b0, b1, b2, b3;
        if (TRANSB) {
            b0 = B[(c0+0)*LD + k]; b1 = B[(c0+1)*LD + k];
            b2 = B[(c0+2)*LD + k]; b3 = B[(c0+3)*LD + k];
        } else {
            b0 = B[k*LD + c0+0]; b1 = B[k*LD + c0+1];
            b2 = B[k*LD + c0+2]; b3 = B[k*LD + c0+3];
        }
        acc[0][0] += a0*b0; acc[0][1] += a0*b1; acc[0][2] += a0*b2; acc[0][3] += a0*b3;
        acc[1][0] += a1*b0; acc[1][1] += a1*b1; acc[1][2] += a1*b2; acc[1][3] += a1*b3;
        acc[2][0] += a2*b0; acc[2][1] += a2*b1; acc[2][2] += a2*b2; acc[2][3] += a2*b3;
        acc[3][0] += a3*b0; acc[3][1] += a3*b1; acc[3][2] += a3*b2; acc[3][3] += a3*b3;
    }
    #pragma unroll
    for (int i = 0; i < 4; i++)
        #pragma unroll
        for (int j = 0; j < 4; j++)
            C[(size_t)(r0+i)*ldc + c0 + j] = acc[i][j];
}

// C = A^T * B (both smem, stride LD)
__device__ __forceinline__ void mm64_tA(const float* __restrict__ A,
                                        const float* __restrict__ B,
                                        float* __restrict__ C) {
    const int tid = threadIdx.x;
    const int r0 = (tid >> 4) << 2;
    const int c0 = (tid & 15) << 2;
    float acc[4][4];
    #pragma unroll
    for (int i = 0; i < 4; i++)
        #pragma unroll
        for (int j = 0; j < 4; j++) acc[i][j] = 0.0f;
    #pragma unroll 4
    for (int k = 0; k < 64; k++) {
        float a0 = A[k*LD + r0+0];
        float a1 = A[k*LD + r0+1];
        float a2 = A[k*LD + r0+2];
        float a3 = A[k*LD + r0+3];
        float b0 = B[k*LD + c0+0], b1 = B[k*LD + c0+1];
        float b2 = B[k*LD + c0+2], b3 = B[k*LD + c0+3];
        acc[0][0] += a0*b0; acc[0][1] += a0*b1; acc[0][2] += a0*b2; acc[0][3] += a0*b3;
        acc[1][0] += a1*b0; acc[1][1] += a1*b1; acc[1][2] += a1*b2; acc[1][3] += a1*b3;
        acc[2][0] += a2*b0; acc[2][1] += a2*b1; acc[2][2] += a2*b2; acc[2][3] += a2*b3;
        acc[3][0] += a3*b0; acc[3][1] += a3*b1; acc[3][2] += a3*b2; acc[3][3] += a3*b3;
    }
    #pragma unroll
    for (int i = 0; i < 4; i++)
        #pragma unroll
        for (int j = 0; j < 4; j++)
            C[(r0+i)*LD + c0 + j] = acc[i][j];
}

__device__ __forceinline__ void symmetrize(const float* __restrict__ S, float* __restrict__ D) {
    for (int i = threadIdx.x; i < MATSZ; i += 256) {
        int r = i >> 6, c = i & 63;
        D[r*LD+c] = 0.5f*(S[r*LD+c] + S[c*LD+r]);
    }
}

// ---- two-sided Jacobi (per-domain kernels; handles indefinite) ----
template<bool INITV>
__device__ void jacobi_eig(float* A, float* V, float tol) {
    const int tid  = threadIdx.x;
    const int warp = tid >> 5;
    const int lane = tid & 31;
    const unsigned FULL = 0xffffffffu;
    if (INITV) {
        for (int i = tid; i < MATSZ; i += 256) {
            int r = i >> 6, c = i & 63;
            V[r*LD+c] = (r == c) ? 1.0f : 0.0f;
        }
        __syncthreads();
    }
    for (int sw = 0; sw < MAXSWEEPS; sw++) {
        float offs = 0.0f, tots = 0.0f;
        for (int i = tid; i < MATSZ; i += 256) {
            int r = i >> 6, c = i & 63;
            float a = A[r*LD+c], a2 = a*a;
            tots += a2;
            if (r != c) offs += a2;
        }
        float offT = blockReduceSum(offs);
        float totT = blockReduceSum(tots);
        if (offT <= tol * totT + 1e-30f) break;

        for (int rd = 0; rd < 63; rd++) {
            const int x = (rd * 32) % 63;
            int myp = 0, myq = 0; float myc = 1.0f, mys = 0.0f;
            if (lane < 4) {
                const int slot = warp * 4 + lane;
                if (slot == 0) { myp = x; myq = 63; }
                else {
                    int a = x + slot; if (a >= 63) a -= 63;
                    int b = x - slot; if (b < 0)   b += 63;
                    myp = min(a, b); myq = max(a, b);
                }
                const float apq = A[myp*LD+myq];
                const float app = A[myp*LD+myp];
                const float aqq = A[myq*LD+myq];
                if (fabsf(apq) > 2e-7f * (fabsf(app) + fabsf(aqq))) {
                    const float tau = (aqq - app) / (2.0f * apq);
                    float t = 1.0f / (fabsf(tau) + sqrtf(1.0f + tau*tau));
                    if (tau < 0.0f) t = -t;
                    myc = rsqrtf(1.0f + t*t);
                    mys = t * myc;
                }
            }
            int pp[4], qq[4]; float cc[4], ssv[4];
            #pragma unroll
            for (int t = 0; t < 4; t++) {
                pp[t]  = __shfl_sync(FULL, myp, t);
                qq[t]  = __shfl_sync(FULL, myq, t);
                cc[t]  = __shfl_sync(FULL, myc, t);
                ssv[t] = __shfl_sync(FULL, mys, t);
            }
            #pragma unroll
            for (int t = 0; t < 4; t++) {
                const float c = cc[t], s = ssv[t];
                if (s != 0.0f) {
                    float* Ap = A + pp[t]*LD;
                    float* Aq = A + qq[t]*LD;
                    #pragma unroll
                    for (int kk = 0; kk < 2; kk++) {
                        const int k = lane + 32*kk;
                        const float ap = Ap[k], aq = Aq[k];
                        Ap[k] = c*ap - s*aq;
                        Aq[k] = s*ap + c*aq;
                    }
                }
            }
            __syncthreads();
            float* Ar0 = A + lane*LD;
            float* Vr0 = V + lane*LD;
            #pragma unroll
            for (int t = 0; t < 4; t++) {
                const float c = cc[t], s = ssv[t];
                if (s != 0.0f) {
                    const int p = pp[t], q = qq[t];
                    #pragma unroll
                    for (int kk = 0; kk < 2; kk++) {
                        float* Ar = Ar0 + 32*LD*kk;
                        float* Vr = Vr0 + 32*LD*kk;
                        const float ap = Ar[p], aq = Ar[q];
                        Ar[p] = c*ap - s*aq;
                        Ar[q] = s*ap + c*aq;
                        const float vp = Vr[p], vq = Vr[q];
                        Vr[p] = c*vp - s*vq;
                        Vr[q] = s*vp + c*vq;
                    }
                }
            }
            __syncthreads();
        }
    }
}

// ---- register-resident one-sided Jacobi (SPD), Brent-Luk odd-even ordering ----
// Bm (smem, stride LD): SPD matrix in; on exit Bm columns = ORTHONORMAL eigenvectors
// (arbitrary order/sign), lam[j] = eigenvalue of column j.
// 32 workers x 8 threads; each worker holds 2 columns in registers.
// A-rounds: intra-worker (register-only). B-rounds: neighbor exchange via shfl
// (warp-internal) or a tiny smem staging buffer (7 warp boundaries).
__device__ void jacobi_os_reg(float* Bm, float* lam) {
    __shared__ float xb[7*64];
    __shared__ float xbn[8];
    __shared__ int chg;
    const int tid = threadIdx.x;
    const int w   = tid >> 3;        // worker 0..31
    const int g   = tid & 7;
    const int ww  = w & 3;           // worker within warp
    const int wp  = w >> 2;          // warp id
    const unsigned FULL = 0xffffffffu;
    float P[8], Q[8], R[8], xs[8];
    #pragma unroll
    for (int i = 0; i < 8; i++) {
        int k = g + 8*i;
        P[i] = Bm[k*LD + 2*w];
        Q[i] = Bm[k*LD + 2*w + 1];
    }
    if (tid == 0) chg = 0;
    __syncthreads();
    for (int sw = 0; sw < MAXSWEEPS; sw++) {
        // fresh carried norms each sweep
        float nP = 0.0f, nQ = 0.0f;
        #pragma unroll
        for (int i = 0; i < 8; i++) { nP += P[i]*P[i]; nQ += Q[i]*Q[i]; }
        #pragma unroll
        for (int o = 4; o; o >>= 1) { nP += __shfl_xor_sync(FULL, nP, o); nQ += __shfl_xor_sync(FULL, nQ, o); }
        for (int half = 0; half < 32; half++) {
            // ---------- A round: pair (2w, 2w+1), register-only ----------
            float d = 0.0f;
            #pragma unroll
            for (int i = 0; i < 8; i++) d += P[i]*Q[i];
            #pragma unroll
            for (int o = 4; o; o >>= 1) d += __shfl_xor_sync(FULL, d, o);
            if (d*d > 4e-14f * nP * nQ) {
                float tau = (nQ - nP) / (2.0f * d);
                float t = 1.0f / (fabsf(tau) + sqrtf(1.0f + tau*tau));
                if (tau < 0.0f) t = -t;
                float c = rsqrtf(1.0f + t*t), s = t*c;
                #pragma unroll
                for (int i = 0; i < 8; i++) {
                    float x = P[i], y = Q[i];
                    P[i] = s*x + c*y;        // y' -> pos 2w   (swap)
                    Q[i] = c*x - s*y;        // x' -> pos 2w+1
                }
                float tcs = 2.0f*c*s*d;
                float nPn = s*s*nP + tcs + c*c*nQ;
                float nQn = c*c*nP - tcs + s*s*nQ;
                nP = nPn; nQ = nQn;
                if (g == 0) chg = 1;
            } else {
                #pragma unroll
                for (int i = 0; i < 8; i++) { float x = P[i]; P[i] = Q[i]; Q[i] = x; }
                float x = nP; nP = nQ; nQ = x;
            }
            // ---------- B round: pair (2w+1, 2w+2) ----------
            // stage 1: obtain R = P of worker w+1
            if (ww == 0 && wp > 0) {
                #pragma unroll
                for (int i = 0; i < 8; i++) xb[(wp-1)*64 + g + 8*i] = P[i];
                if (g == 0) xbn[wp-1] = nP;
            }
            __syncthreads();
            float nR;
            #pragma unroll
            for (int i = 0; i < 8; i++) R[i] = __shfl_down_sync(FULL, P[i], 8);
            nR = __shfl_down_sync(FULL, nP, 8);
            if (ww == 3 && wp < 7) {
                #pragma unroll
                for (int i = 0; i < 8; i++) R[i] = xb[wp*64 + g + 8*i];
                nR = xbn[wp];
            }
            const bool doPair = (w <= 30);
            float d2 = 0.0f;
            #pragma unroll
            for (int i = 0; i < 8; i++) d2 += Q[i]*R[i];
            #pragma unroll
            for (int o = 4; o; o >>= 1) d2 += __shfl_xor_sync(FULL, d2, o);
            float nXs;
            if (doPair && d2*d2 > 4e-14f * nQ * nR) {
                float tau = (nR - nQ) / (2.0f * d2);
                float t = 1.0f / (fabsf(tau) + sqrtf(1.0f + tau*tau));
                if (tau < 0.0f) t = -t;
                float c = rsqrtf(1.0f + t*t), s = t*c;
                #pragma unroll
                for (int i = 0; i < 8; i++) {
                    float x = Q[i], y = R[i];
                    xs[i] = c*x - s*y;       // x' -> pos 2w+2 (send to w+1)
                    Q[i]  = s*x + c*y;       // y' -> pos 2w+1
                }
                float tcs = 2.0f*c*s*d2;
                nXs = c*c*nQ - tcs + s*s*nR;
                nQ  = s*s*nQ + tcs + c*c*nR;
                if (g == 0) chg = 1;
            } else {
                #pragma unroll
                for (int i = 0; i < 8; i++) xs[i] = Q[i];
                nXs = nQ;
                if (doPair) {
                    #pragma unroll
                    for (int i = 0; i < 8; i++) Q[i] = R[i];
                    nQ = nR;
                }
            }
            // stage 2: send xs -> worker w+1's new P
            if (ww == 3 && wp < 7) {
                #pragma unroll
                for (int i = 0; i < 8; i++) xb[wp*64 + g + 8*i] = xs[i];
                if (g == 0) xbn[wp] = nXs;
            }
            __syncthreads();
            #pragma unroll
            for (int i = 0; i < 8; i++) R[i] = __shfl_up_sync(FULL, xs[i], 8);
            nR = __shfl_up_sync(FULL, nXs, 8);
            if (ww == 0 && wp > 0) {
                #pragma unroll
                for (int i = 0; i < 8; i++) R[i] = xb[(wp-1)*64 + g + 8*i];
                nR = xbn[wp-1];
            }
            if (w >= 1) {
                #pragma unroll
                for (int i = 0; i < 8; i++) P[i] = R[i];
                nP = nR;
            }
        }
        int c = chg;
        __syncthreads();
        if (c == 0) break;
        if (tid == 0) chg = 0;
        __syncthreads();
    }
    // normalized eigenvector columns + eigenvalues (fresh norms)
    float a = 0.0f, b = 0.0f;
    #pragma unroll
    for (int i = 0; i < 8; i++) { a += P[i]*P[i]; b += Q[i]*Q[i]; }
    #pragma unroll
    for (int o = 4; o; o >>= 1) { a += __shfl_xor_sync(FULL, a, o); b += __shfl_xor_sync(FULL, b, o); }
    float la = sqrtf(a), lb = sqrtf(b);
    float ia = 1.0f / fmaxf(la, 1e-20f), ib = 1.0f / fmaxf(lb, 1e-20f);
    #pragma unroll
    for (int i = 0; i < 8; i++) {
        int k = g + 8*i;
        Bm[k*LD + 2*w]     = P[i]*ia;
        Bm[k*LD + 2*w + 1] = Q[i]*ib;
    }
    if (g == 0) { lam[2*w] = la; lam[2*w+1] = lb; }
    __syncthreads();
}

// ---------------- kernels ----------------
__global__ void kzero_kernel() {
    int i = blockIdx.x * blockDim.x + threadIdx.x;
    int stride = gridDim.x * blockDim.x;
    for (int j = i; j < NDOMS*MATSZ; j += stride) { g_bmsum[j] = 0.0f; g_GT[j] = 0.0f; }
    if (i < NDOMS) g_sumsq[i] = 0.0f;
}

__global__ void __launch_bounds__(256) k1_kernel(const float* __restrict__ X,
                                                 const int* __restrict__ dd) {
    __shared__ int sdom[128];
    const int e  = blockIdx.x * 256 + threadIdx.x;
    const int n0 = blockIdx.y * 128;
    if (threadIdx.x < 128) sdom[threadIdx.x] = dd[n0 + threadIdx.x];
    __syncthreads();
    float acc[NDOMS];
    #pragma unroll
    for (int k = 0; k < NDOMS; k++) acc[k] = 0.0f;
    for (int m = 0; m < 128; m++) {
        float x = X[(size_t)(n0 + m) * MATSZ + e];
        int dom = sdom[m];
        #pragma unroll
        for (int k = 0; k < NDOMS; k++) acc[k] += (dom == k) ? x : 0.0f;
    }
    #pragma unroll
    for (int k = 0; k < NDOMS; k++) atomicAdd(&g_bmsum[k*MATSZ + e], acc[k]);
}

__global__ void __launch_bounds__(256) k2_kernel(const int* __restrict__ dd) {
    extern __shared__ float sm[];
    float* SX = sm; float* SA = sm + BUF; float* SV = sm + 2*BUF;
    __shared__ float sl[64];
    const int dom = blockIdx.x, tid = threadIdx.x;

    float loc = 0.0f;
    for (int i = tid; i < NMAT; i += 256) loc += (dd[i] == dom) ? 1.0f : 0.0f;
    float cnt  = blockReduceSum(loc);
    float cntf = fmaxf(cnt, 1.0f);
    if (tid == 0) g_cnt[dom] = cntf;

    for (int i = tid; i < MATSZ; i += 256) {
        int r = i >> 6, c = i & 63;
        SX[r*LD+c] = g_bmsum[dom*MATSZ + i] / cntf;
    }
    __syncthreads();
    symmetrize(SX, SA);
    __syncthreads();
    jacobi_eig<true>(SA, SV, 1e-8f);
    if (tid < 64) sl[tid] = fmaxf(SA[tid*LD+tid], EIG_EPS);
    __syncthreads();
    for (int i = tid; i < MATSZ; i += 256) {
        int r = i >> 6, c = i & 63;
        SX[r*LD+c] = SV[r*LD+c] * sqrtf(sl[c]);
    }
    __syncthreads();
    mm64<true>(SX, SV, g_bm_sq + dom*MATSZ, 64);
    __syncthreads();
    for (int i = tid; i < MATSZ; i += 256) {
        int r = i >> 6, c = i & 63;
        SX[r*LD+c] = SV[r*LD+c] / sqrtf(sl[c]);
    }
    __syncthreads();
    mm64<true>(SX, SV, g_bm_isq + dom*MATSZ, 64);
}

// per-element: eig of M3 = bm_isq X bm_isq (register one-sided); XT -> g_XT, V3 -> g_V3.
__global__ void __launch_bounds__(256) k3_kernel(const float* __restrict__ X,
                                                 const int* __restrict__ dd) {
    extern __shared__ float sm[];
    float* S0 = sm; float* S1 = sm + BUF; float* S2 = sm + 2*BUF;
    __shared__ float lam[64], sl[64];
    const int n = blockIdx.x, tid = threadIdx.x;
    const int dom = dd[n];
    g2s(X + (size_t)n * MATSZ, S0);
    g2s(g_bm_isq + dom * MATSZ, S1);
    __syncthreads();
    mm64<false>(S1, S0, S2, LD);  __syncthreads();   // T = Q·X
    mm64<false>(S2, S1, S0, LD);  __syncthreads();   // M = T·Q -> S0
    symmetrize(S0, S1);           __syncthreads();   // A -> S1
    jacobi_os_reg(S1, lam);                          // S1 := V3 (orthonormal cols)
    if (tid < 64) sl[tid] = logf(fmaxf(lam[tid], EIG_EPS));
    __syncthreads();
    float lv = (tid < 64) ? sl[tid] : 0.0f;
    float sq = blockReduceSum(lv * lv);
    if (tid == 0) atomicAdd(&g_sumsq[dom], sq);
    for (int i = tid; i < MATSZ; i += 256) {
        int r = i >> 6, c = i & 63;
        S0[r*LD+c] = S1[r*LD+c] * sl[c];             // W = V3·diag(logλ)
    }
    __syncthreads();
    s2g(S1, g_V3 + (size_t)n * MATSZ);
    mm64<true>(S0, S1, g_XT + (size_t)n * MATSZ, 64);  // XT = W·V3^T
}

__global__ void __launch_bounds__(256) k3b_kernel(const int* __restrict__ dd) {
    __shared__ int sdom[128];
    const int e  = blockIdx.x * 256 + threadIdx.x;
    const int n0 = blockIdx.y * 128;
    if (threadIdx.x < 128) sdom[threadIdx.x] = dd[n0 + threadIdx.x];
    __syncthreads();
    float acc[NDOMS];
    #pragma unroll
    for (int k = 0; k < NDOMS; k++) acc[k] = 0.0f;
    for (int m = 0; m < 128; m++) {
        float x = g_XT[(size_t)(n0 + m) * MATSZ + e];
        int dom = sdom[m];
        #pragma unroll
        for (int k = 0; k < NDOMS; k++) acc[k] += (dom == k) ? x : 0.0f;
    }
    #pragma unroll
    for (int k = 0; k < NDOMS; k++) atomicAdd(&g_GT[k*MATSZ + e], acc[k]);
}

// per-domain (ETA=1 exact): rm = bm_sq expm(GT) bm_sq; GT2 = GT; var = sumsq/cnt - ||GT||^2.
__global__ void __launch_bounds__(256) k4_kernel(const float* __restrict__ mean,
                                                 const float* __restrict__ stdv) {
    extern __shared__ float sm[];
    float* SA = sm;           float* SV = sm + BUF;
    float* SQ = sm + 2*BUF;   float* SX = sm + 3*BUF;
    float* SG = sm + 4*BUF;
    __shared__ float sl[64];
    const int tid = threadIdx.x, b = blockIdx.x;

    if (b == NDOMS) {
        float dev = 0.0f;
        for (int i = tid; i < MATSZ; i += 256) {
            int r = i >> 6, c = i & 63;
            float mv = mean[i];
            SX[r*LD+c] = mv;
            dev += fabsf(mv - ((r == c) ? 1.0f : 0.0f));
        }
        float devT = blockReduceSum(dev);
        if (tid == 0) g_noBsq = (devT < 1e-6f) ? 1 : 0;
        __syncthreads();
        symmetrize(SX, SA); __syncthreads();
        jacobi_eig<true>(SA, SV, 1e-8f);
        if (tid < 64) sl[tid] = sqrtf(fmaxf(SA[tid*LD+tid], EIG_EPS));
        __syncthreads();
        for (int i = tid; i < MATSZ; i += 256) { int r=i>>6,c=i&63; SX[r*LD+c] = SV[r*LD+c]*sl[c]; }
        __syncthreads();
        mm64<true>(SX, SV, g_Bsq, 64);
        return;
    }
    const int dom = b;
    const float cntf = g_cnt[dom];
    float gn = 0.0f;
    for (int i = tid; i < MATSZ; i += 256) {
        int r = i >> 6, c = i & 63;
        float g = g_GT[dom*MATSZ+i] / cntf;
        SG[r*LD+c] = g;
        gn += g * g;
    }
    float gnorm2 = blockReduceSum(gn);
    __syncthreads();
    symmetrize(SG, SA); __syncthreads();
    jacobi_eig<true>(SA, SV, 1e-8f);        // eig(GT), indefinite
    if (tid < 64) sl[tid] = expf(SA[tid*LD+tid]);
    __syncthreads();
    for (int i = tid; i < MATSZ; i += 256) { int r=i>>6,c=i&63; SX[r*LD+c] = SV[r*LD+c]*sl[c]; }
    __syncthreads();
    mm64<true>(SX, SV, SQ, LD); __syncthreads();      // E = expm(GT)
    for (int i = tid; i < MATSZ; i += 256) { int r=i>>6,c=i&63; SA[r*LD+c] = g_bm_sq[dom*MATSZ+i]; }
    __syncthreads();
    mm64<false>(SA, SQ, SX, LD); __syncthreads();     // bm_sq·E
    mm64<false>(SX, SA, SV, LD); __syncthreads();     // rm
    symmetrize(SV, SA); __syncthreads();
    jacobi_eig<true>(SA, SQ, 1e-8f);                  // eig(rm)
    if (tid < 64) sl[tid] = fmaxf(SA[tid*LD+tid], EIG_EPS);
    __syncthreads();
    for (int i = tid; i < MATSZ; i += 256) { int r=i>>6,c=i&63; SX[r*LD+c] = SQ[r*LD+c]*rsqrtf(sl[c]); }
    __syncthreads();
    mm64<true>(SX, SQ, g_rm_isq + dom*MATSZ, 64);
    if (tid == 0) {
        float var = g_sumsq[dom] / cntf - gnorm2;
        g_s[dom]  = stdv[0] / sqrtf(var + EPS_C);
    }
}

// per-element normalize, warm-started: A' = V3^T M5 V3 (near-diagonal, SPD).
__global__ void __launch_bounds__(256) k5_kernel(const float* __restrict__ X,
                                                 const int* __restrict__ dd,
                                                 float* __restrict__ out) {
    extern __shared__ float sm[];
    float* S0 = sm; float* S1 = sm + BUF; float* S2 = sm + 2*BUF;
    __shared__ float lam[64], ff[64];
    const int n = blockIdx.x, tid = threadIdx.x;
    const int dom = dd[n];
    const int noB = g_noBsq;
    g2s(X + (size_t)n * MATSZ, S0);
    g2s(g_rm_isq + dom * MATSZ, S1);
    __syncthreads();
    mm64<false>(S1, S0, S2, LD);  __syncthreads();   // T = Q5·X
    mm64<false>(S2, S1, S0, LD);  __syncthreads();   // M5 -> S0
    g2s(g_V3 + (size_t)n * MATSZ, S1);               // V3 -> S1
    __syncthreads();
    mm64<false>(S0, S1, S2, LD);  __syncthreads();   // M5·V3 -> S2
    mm64_tA(S1, S2, S0);          __syncthreads();   // A' = V3^T·(M5·V3) -> S0
    symmetrize(S0, S2);           __syncthreads();   // A -> S2
    jacobi_os_reg(S2, lam);                          // S2 := V' (orthonormal)
    const float sgl = g_s[dom];
    if (tid < 64) ff[tid] = expf(sgl * logf(fmaxf(lam[tid], EIG_EPS)));
    __syncthreads();
    mm64<false>(S1, S2, S0, LD);  __syncthreads();   // G = V3·V' -> S0
    for (int i = tid; i < MATSZ; i += 256) {
        int r = i >> 6, c = i & 63;
        S1[r*LD+c] = S0[r*LD+c] * ff[c];             // W2 = G·diag(λ^s)
    }
    __syncthreads();
    if (noB) {
        mm64<true>(S1, S0, out + (size_t)n * MATSZ, 64);    // Xn = W2·G^T
    } else {
        mm64<true>(S1, S0, S2, LD);   __syncthreads();      // P -> S2
        g2s(g_Bsq, S0);               __syncthreads();
        mm64<false>(S0, S2, S1, LD);  __syncthreads();      // Bsq·P
        mm64<false>(S1, S0, out + (size_t)n * MATSZ, 64);   // Xn
    }
}

// ---------------- launch ----------------
extern "C" void kernel_launch(void* const* d_in, const int* in_sizes, int n_in,
                              void* d_out, int out_size) {
    const float* X    = (const float*)d_in[0];
    const int*   dd   = (const int*)  d_in[1];
    const float* mean = (const float*)d_in[2];
    const float* stdv = (const float*)d_in[3];
    float* out = (float*)d_out;

    const int SM3 = 3 * BUF * (int)sizeof(float);
    const int SM5 = 5 * BUF * (int)sizeof(float);
    cudaFuncSetAttribute(k2_kernel, cudaFuncAttributeMaxDynamicSharedMemorySize, SM3);
    cudaFuncSetAttribute(k3_kernel, cudaFuncAttributeMaxDynamicSharedMemorySize, SM3);
    cudaFuncSetAttribute(k4_kernel, cudaFuncAttributeMaxDynamicSharedMemorySize, SM5);
    cudaFuncSetAttribute(k5_kernel, cudaFuncAttributeMaxDynamicSharedMemorySize, SM3);

    kzero_kernel<<<128, 256>>>();
    k1_kernel<<<dim3(16, 32), 256>>>(X, dd);
    k2_kernel<<<NDOMS, 256, SM3>>>(dd);
    k3_kernel<<<NMAT, 256, SM3>>>(X, dd);
    k3b_kernel<<<dim3(16, 32), 256>>>(dd);
    k4_kernel<<<NDOMS + 1, 256, SM5>>>(mean, stdv);
    k5_kernel<<<NMAT, 256, SM3>>>(X, dd, out);
}